// round 11
// baseline (speedup 1.0000x reference)
#include <cuda_runtime.h>
#include <cuda_bf16.h>
#include <cstdint>
#include <math.h>

#define NROWS 8192
#define FDIM  256
#define EPS   1e-5f
#define SLOPE 0.01f
#define MAXD  128
#define SCAN_BLOCKS 296

typedef __nv_bfloat16 bf16;

// -------- scratch (device globals) --------
__device__ bf16  g_x_hi[2][NROWS * 128];
__device__ bf16  g_x_lo[2][NROWS * 128];
__device__ bf16  g_w1t_hi[3][FDIM * 128];
__device__ bf16  g_w1t_lo[3][FDIM * 128];
__device__ bf16  g_w2t_hi[3][FDIM * FDIM];
__device__ bf16  g_w2t_lo[3][FDIM * FDIM];
__device__ bf16  g_h1_hi[3][NROWS * FDIM];
__device__ bf16  g_h1_lo[3][NROWS * FDIM];
__device__ float g_h2[3][NROWS * FDIM];
__device__ float g_sum[3][FDIM];
__device__ float g_sumsq[3][FDIM];
__device__ int   g_deg[NROWS];
__device__ int   g_nbr[NROWS * MAXD];

// -------- fused prep --------
__global__ void prep_kernel(const float* __restrict__ q, const float* __restrict__ k,
                            const float* __restrict__ w1q, const float* __restrict__ w1k,
                            const float* __restrict__ w1v,
                            const float* __restrict__ w2q, const float* __restrict__ w2k,
                            const float* __restrict__ w2v)
{
    const int idx = blockIdx.x * 256 + threadIdx.x;
    const int stride = gridDim.x * 256;
    const int NX = NROWS * 128;

    for (int i = idx; i < 3 * FDIM; i += stride) {
        ((float*)g_sum)[i] = 0.f;
        ((float*)g_sumsq)[i] = 0.f;
    }
    for (int i = idx; i < NX; i += stride) {
        float v = q[i];
        bf16 h = __float2bfloat16(v);
        g_x_hi[0][i] = h;
        g_x_lo[0][i] = __float2bfloat16(v - __bfloat162float(h));
        float v2 = k[i];
        bf16 h2 = __float2bfloat16(v2);
        g_x_hi[1][i] = h2;
        g_x_lo[1][i] = __float2bfloat16(v2 - __bfloat162float(h2));
    }
    const float* W1[3] = { w1q, w1k, w1v };
    for (int p = 0; p < 3; ++p) {
        const float* w = W1[p];
        for (int i = idx; i < 128 * FDIM; i += stride) {
            int kk = i / FDIM, n = i % FDIM;
            float v = w[i];
            bf16 h = __float2bfloat16(v);
            g_w1t_hi[p][n * 128 + kk] = h;
            g_w1t_lo[p][n * 128 + kk] = __float2bfloat16(v - __bfloat162float(h));
        }
    }
    const float* W2[3] = { w2q, w2k, w2v };
    for (int p = 0; p < 3; ++p) {
        const float* w = W2[p];
        for (int i = idx; i < FDIM * FDIM; i += stride) {
            int kk = i / FDIM, n = i % FDIM;
            float v = w[i];
            bf16 h = __float2bfloat16(v);
            g_w2t_hi[p][n * FDIM + kk] = h;
            g_w2t_lo[p][n * FDIM + kk] = __float2bfloat16(v - __bfloat162float(h));
        }
    }
}

#define MMA_BF16(d, a, b) \
    asm volatile("mma.sync.aligned.m16n8k16.row.col.f32.bf16.bf16.f32 " \
                 "{%0,%1,%2,%3}, {%4,%5,%6,%7}, {%8,%9}, {%0,%1,%2,%3};" \
                 : "+f"(d[0]), "+f"(d[1]), "+f"(d[2]), "+f"(d[3]) \
                 : "r"(a[0]), "r"(a[1]), "r"(a[2]), "r"(a[3]), "r"(b[0]), "r"(b[1]))

#define LDSM4(r, a) \
    asm volatile("ldmatrix.sync.aligned.m8n8.x4.shared.b16 {%0,%1,%2,%3}, [%4];" \
                 : "=r"((r)[0]), "=r"((r)[1]), "=r"((r)[2]), "=r"((r)[3]) : "r"(a))

__device__ __forceinline__ unsigned smem_u32(const void* p) {
    return (unsigned)__cvta_generic_to_shared(p);
}
#define CP16(dst, src) \
    asm volatile("cp.async.cg.shared.global [%0], [%1], 16;" :: "r"(dst), "l"(src))

// stage: A hi/lo 64x40, B hi/lo 64x40 (bf16) = 10240 elems = 20KB
#define ST_ELEMS 10240
#define OFF_AH 0
#define OFF_AL 2560
#define OFF_BH 5120
#define OFF_BL 7680

extern __shared__ bf16 dsm[];

// -------- GEMM core: TM=64, TN=64, 8 warps (2m x 4n), warp 32x16 --------
template<int STATS>
__device__ __forceinline__ void gemm_core(
    const bf16* __restrict__ Ahi, const bf16* __restrict__ Alo,
    const bf16* __restrict__ Bhi, const bf16* __restrict__ Blo,
    const float* __restrict__ bias, int K,
    bf16* __restrict__ OutHi, bf16* __restrict__ OutLo,
    float* __restrict__ OutF, float* __restrict__ gsum, float* __restrict__ gsq)
{
    const int tid  = threadIdx.x;
    const int lane = tid & 31, wid = tid >> 5;
    const int g = lane >> 2, tg = lane & 3;
    const int wm = (wid >> 2) * 32;
    const int wn = (wid & 3) * 16;
    const int bm = blockIdx.y * 64, bn = blockIdx.x * 64;

    const int r_ld  = tid >> 2;
    const int cg_ld = (tid & 3) * 8;

    const unsigned offA = (unsigned)(((lane & 7) + ((lane >> 3) & 1) * 8) * 40 + (lane >> 4) * 8);
    const unsigned offB = (unsigned)(((lane & 7) + (lane >> 4) * 8) * 40 + ((lane >> 3) & 1) * 8);

    float acc[2][2][4];
    #pragma unroll
    for (int mt = 0; mt < 2; ++mt)
        #pragma unroll
        for (int nt = 0; nt < 2; ++nt)
            #pragma unroll
            for (int c = 0; c < 4; ++c) acc[mt][nt][c] = 0.f;

    const int nchunks = K >> 5;

    auto load_stage = [&](int st, int k0) {
        bf16* base = dsm + st * ST_ELEMS;
        CP16(smem_u32(base + OFF_AH + r_ld * 40 + cg_ld),
             Ahi + (size_t)(bm + r_ld) * K + k0 + cg_ld);
        CP16(smem_u32(base + OFF_AL + r_ld * 40 + cg_ld),
             Alo + (size_t)(bm + r_ld) * K + k0 + cg_ld);
        CP16(smem_u32(base + OFF_BH + r_ld * 40 + cg_ld),
             Bhi + (size_t)(bn + r_ld) * K + k0 + cg_ld);
        CP16(smem_u32(base + OFF_BL + r_ld * 40 + cg_ld),
             Blo + (size_t)(bn + r_ld) * K + k0 + cg_ld);
        asm volatile("cp.async.commit_group;");
    };

    load_stage(0, 0);

    for (int c = 0; c < nchunks; ++c) {
        const int cur = c & 1;
        if (c + 1 < nchunks) {
            load_stage(cur ^ 1, (c + 1) * 32);
            asm volatile("cp.async.wait_group 1;");
        } else {
            asm volatile("cp.async.wait_group 0;");
        }
        __syncthreads();

        const unsigned sb = smem_u32(dsm + cur * ST_ELEMS);
        const unsigned aAh = sb + (OFF_AH + offA) * 2;
        const unsigned aAl = sb + (OFF_AL + offA) * 2;
        const unsigned aBh = sb + (OFF_BH + offB) * 2;
        const unsigned aBl = sb + (OFF_BL + offB) * 2;

        #pragma unroll
        for (int ks = 0; ks < 2; ++ks) {
            const unsigned kb2 = (unsigned)(ks * 16) * 2;
            unsigned int ah[2][4], al[2][4], bf[4];
            const unsigned tom0 = (unsigned)(wm * 40) * 2 + kb2;
            const unsigned tom1 = (unsigned)((wm + 16) * 40) * 2 + kb2;
            const unsigned ton  = (unsigned)(wn * 40) * 2 + kb2;
            LDSM4(ah[0], aAh + tom0);
            LDSM4(ah[1], aAh + tom1);
            LDSM4(al[0], aAl + tom0);
            LDSM4(al[1], aAl + tom1);
            LDSM4(bf, aBh + ton);
            #pragma unroll
            for (int mt = 0; mt < 2; ++mt) {
                MMA_BF16(acc[mt][0], ah[mt], (&bf[0]));
                MMA_BF16(acc[mt][1], ah[mt], (&bf[2]));
            }
            #pragma unroll
            for (int mt = 0; mt < 2; ++mt) {
                MMA_BF16(acc[mt][0], al[mt], (&bf[0]));
                MMA_BF16(acc[mt][1], al[mt], (&bf[2]));
            }
            LDSM4(bf, aBl + ton);
            #pragma unroll
            for (int mt = 0; mt < 2; ++mt) {
                MMA_BF16(acc[mt][0], ah[mt], (&bf[0]));
                MMA_BF16(acc[mt][1], ah[mt], (&bf[2]));
            }
        }
        __syncthreads();
    }

    float hv[2][2][4];
    #pragma unroll
    for (int mt = 0; mt < 2; ++mt)
        #pragma unroll
        for (int nt = 0; nt < 2; ++nt)
            #pragma unroll
            for (int c = 0; c < 4; ++c) {
                int col = wn + nt * 8 + 2 * tg + (c & 1);
                float v = acc[mt][nt][c] + bias[bn + col];
                hv[mt][nt][c] = (v >= 0.f) ? v : SLOPE * v;
            }

    if (STATS == 0) {
        #pragma unroll
        for (int mt = 0; mt < 2; ++mt)
            #pragma unroll
            for (int nt = 0; nt < 2; ++nt)
                #pragma unroll
                for (int c = 0; c < 4; ++c) {
                    int row = bm + wm + mt * 16 + g + ((c >> 1) ? 8 : 0);
                    int col = bn + wn + nt * 8 + 2 * tg + (c & 1);
                    float v = hv[mt][nt][c];
                    bf16 h = __float2bfloat16(v);
                    size_t idx = (size_t)row * FDIM + col;
                    OutHi[idx] = h;
                    OutLo[idx] = __float2bfloat16(v - __bfloat162float(h));
                }
    } else {
        #pragma unroll
        for (int mt = 0; mt < 2; ++mt)
            #pragma unroll
            for (int nt = 0; nt < 2; ++nt)
                #pragma unroll
                for (int c = 0; c < 4; ++c) {
                    int row = bm + wm + mt * 16 + g + ((c >> 1) ? 8 : 0);
                    int col = bn + wn + nt * 8 + 2 * tg + (c & 1);
                    OutF[(size_t)row * FDIM + col] = hv[mt][nt][c];
                }
        float* csum = (float*)dsm;
        float* csq  = csum + 64;
        if (tid < 128) ((float*)dsm)[tid] = 0.f;
        __syncthreads();
        #pragma unroll
        for (int nt = 0; nt < 2; ++nt)
            #pragma unroll
            for (int p = 0; p < 2; ++p) {
                int col = wn + nt * 8 + 2 * tg + p;
                float a = hv[0][nt][p], b = hv[0][nt][p + 2];
                float c2 = hv[1][nt][p], d = hv[1][nt][p + 2];
                atomicAdd(&csum[col], a + b + c2 + d);
                atomicAdd(&csq[col], a * a + b * b + c2 * c2 + d * d);
            }
        __syncthreads();
        if (tid < 64) {
            atomicAdd(&gsum[bn + tid], csum[tid]);
            atomicAdd(&gsq[bn + tid], csq[tid]);
        }
    }
}

__global__ __launch_bounds__(256, 4) void gemm_l1(const float* __restrict__ b1q,
                                                  const float* __restrict__ b1k,
                                                  const float* __restrict__ b1v)
{
    const int p = blockIdx.z;
    const int xi = (p == 0) ? 0 : 1;
    const float* bias = (p == 0) ? b1q : ((p == 1) ? b1k : b1v);
    gemm_core<0>(g_x_hi[xi], g_x_lo[xi], g_w1t_hi[p], g_w1t_lo[p], bias, 128,
                 g_h1_hi[p], g_h1_lo[p], nullptr, nullptr, nullptr);
}

__global__ __launch_bounds__(256, 4) void gemm_l2(const float* __restrict__ b2q,
                                                  const float* __restrict__ b2k,
                                                  const float* __restrict__ b2v)
{
    const int p = blockIdx.z;
    const float* bias = (p == 0) ? b2q : ((p == 1) ? b2k : b2v);
    gemm_core<1>(g_h1_hi[p], g_h1_lo[p], g_w2t_hi[p], g_w2t_lo[p], bias, FDIM,
                 nullptr, nullptr, g_h2[p], g_sum[p], g_sumsq[p]);
}

// -------- scan: persistent grid-stride CSR build (co-residency-friendly) --------
__global__ __launch_bounds__(256) void scan_kernel(const float* __restrict__ A)
{
    const int tid = threadIdx.x;
    const int lane = tid & 31, wid = tid >> 5;
    __shared__ int wtot[8];

    for (int i = blockIdx.x; i < NROWS; i += gridDim.x) {
        const float4* arow = (const float4*)(A + (size_t)i * NROWS);
        float4 vals[8];
        int cnt = 0;
        #pragma unroll
        for (int it = 0; it < 8; ++it) {
            vals[it] = __ldcs(arow + tid + it * 256);
            cnt += (vals[it].x != 0.f) + (vals[it].y != 0.f) +
                   (vals[it].z != 0.f) + (vals[it].w != 0.f);
        }

        int incl = cnt;
        #pragma unroll
        for (int o = 1; o < 32; o <<= 1) {
            int v = __shfl_up_sync(0xffffffffu, incl, o);
            if (lane >= o) incl += v;
        }
        if (lane == 31) wtot[wid] = incl;
        __syncthreads();
        int base = 0, total = 0;
        #pragma unroll
        for (int w = 0; w < 8; ++w) {
            int t = wtot[w];
            if (w < wid) base += t;
            total += t;
        }
        int pos = base + incl - cnt;
        int* nb = g_nbr + (size_t)i * MAXD;
        #pragma unroll
        for (int it = 0; it < 8; ++it) {
            int b4 = (tid + it * 256) * 4;
            if (vals[it].x != 0.f) { if (pos < MAXD) nb[pos] = b4 + 0; pos++; }
            if (vals[it].y != 0.f) { if (pos < MAXD) nb[pos] = b4 + 1; pos++; }
            if (vals[it].z != 0.f) { if (pos < MAXD) nb[pos] = b4 + 2; pos++; }
            if (vals[it].w != 0.f) { if (pos < MAXD) nb[pos] = b4 + 3; pos++; }
        }
        if (tid == 0) g_deg[i] = (total > MAXD) ? MAXD : total;
        __syncthreads();   // protect wtot before next iteration
    }
}

// -------- attention compute on CSR (no A access) --------
__global__ __launch_bounds__(256) void attn2_kernel(
    const float* __restrict__ gq, const float* __restrict__ bq,
    const float* __restrict__ gk, const float* __restrict__ bk,
    const float* __restrict__ gv, const float* __restrict__ bv,
    float* __restrict__ out)
{
    const int i = blockIdx.x;
    const int tid = threadIdx.x;
    const int lane = tid & 31, wid = tid >> 5;

    __shared__ float qs[FDIM];
    __shared__ int   snbr[MAXD];
    __shared__ float ez[MAXD];
    __shared__ float red[8];
    __shared__ float s_se, s_cst;

    const int total = g_deg[i];
    if (tid < total) snbr[tid] = g_nbr[(size_t)i * MAXD + tid];

    const float inv = 1.0f / NROWS;
    float m0 = g_sum[0][tid] * inv, v0 = g_sumsq[0][tid] * inv - m0 * m0;
    float sq_ = gq[tid] * rsqrtf(v0 + EPS), shq_ = bq[tid] - m0 * sq_;
    float m1 = g_sum[1][tid] * inv, v1 = g_sumsq[1][tid] * inv - m1 * m1;
    float sk_ = gk[tid] * rsqrtf(v1 + EPS), shk_ = bk[tid] - m1 * sk_;
    float m2 = g_sum[2][tid] * inv, v2 = g_sumsq[2][tid] * inv - m2 * m2;
    float sv_ = gv[tid] * rsqrtf(v2 + EPS), shv_ = bv[tid] - m2 * sv_;

    float qn = fmaf(sq_, g_h2[0][(size_t)i * FDIM + tid], shq_);
    qs[tid] = qn * sk_;
    float cpart = qn * shk_;
    #pragma unroll
    for (int o = 16; o; o >>= 1) cpart += __shfl_xor_sync(0xffffffffu, cpart, o);
    if (lane == 0) red[wid] = cpart;
    __syncthreads();
    if (tid == 0) {
        float r = 0.f;
        #pragma unroll
        for (int w = 0; w < 8; ++w) r += red[w];
        s_cst = r;
    }
    __syncthreads();

    const float cst = s_cst;
    const float4* q4 = (const float4*)qs;
    float4 a0 = q4[lane * 2], a1 = q4[lane * 2 + 1];
    const float* Kr = g_h2[1];
    for (int n = wid; n < total; n += 8) {
        const float4* kr = (const float4*)(Kr + (size_t)snbr[n] * FDIM);
        float4 b0 = kr[lane * 2], b1 = kr[lane * 2 + 1];
        float s = a0.x * b0.x + a0.y * b0.y + a0.z * b0.z + a0.w * b0.w
                + a1.x * b1.x + a1.y * b1.y + a1.z * b1.z + a1.w * b1.w;
        #pragma unroll
        for (int o = 16; o; o >>= 1) s += __shfl_xor_sync(0xffffffffu, s, o);
        if (lane == 0) ez[n] = expf((s + cst) * 0.0625f);
    }
    __syncthreads();

    const float* Vr = g_h2[2];
    float num = 0.f, sub = 0.f;
    #pragma unroll 4
    for (int n = 0; n < total; ++n) {
        float v = Vr[(size_t)snbr[n] * FDIM + tid];
        float e = ez[n];
        num = fmaf(e, v, num);
        sub += v;
    }

    float se = 0.f;
    for (int n = tid; n < total; n += 256) se += ez[n];
    #pragma unroll
    for (int o = 16; o; o >>= 1) se += __shfl_xor_sync(0xffffffffu, se, o);
    if (lane == 0) red[wid] = se;
    __syncthreads();
    if (wid == 0) {
        float r = (lane < 8) ? red[lane] : 0.f;
        #pragma unroll
        for (int o = 4; o; o >>= 1) r += __shfl_xor_sync(0xffffffffu, r, o);
        if (lane == 0) s_se = r;
    }
    __syncthreads();
    se = s_se;

    float totalf = (float)total;
    float denom = ((float)NROWS - totalf) + se;
    float o = (NROWS * bv[tid] + sv_ * (num - sub) + shv_ * (se - totalf)) / denom;
    out[(size_t)i * FDIM + tid] = o;
}

// -------- host --------
extern "C" void kernel_launch(void* const* d_in, const int* in_sizes, int n_in,
                              void* d_out, int out_size)
{
    const float* A = (const float*)d_in[0];
    const float* q = (const float*)d_in[1];
    const float* k = (const float*)d_in[2];
    const float* W1[3] = { (const float*)d_in[3],  (const float*)d_in[9],  (const float*)d_in[15] };
    const float* B1[3] = { (const float*)d_in[4],  (const float*)d_in[10], (const float*)d_in[16] };
    const float* W2[3] = { (const float*)d_in[5],  (const float*)d_in[11], (const float*)d_in[17] };
    const float* B2[3] = { (const float*)d_in[6],  (const float*)d_in[12], (const float*)d_in[18] };
    const float* GM[3] = { (const float*)d_in[7],  (const float*)d_in[13], (const float*)d_in[19] };
    const float* BT[3] = { (const float*)d_in[8],  (const float*)d_in[14], (const float*)d_in[20] };

    static int inited = 0;
    static cudaStream_t s_scan;
    static cudaEvent_t ev_fork, ev_scan_done;
    const int SMEM_GEMM = 2 * ST_ELEMS * (int)sizeof(bf16);   // 40960
    if (!inited) {
        cudaFuncSetAttribute(gemm_l1, cudaFuncAttributeMaxDynamicSharedMemorySize, SMEM_GEMM);
        cudaFuncSetAttribute(gemm_l2, cudaFuncAttributeMaxDynamicSharedMemorySize, SMEM_GEMM);
        int lo, hi;
        cudaDeviceGetStreamPriorityRange(&lo, &hi);   // lo = lowest priority value
        cudaStreamCreateWithPriority(&s_scan, cudaStreamNonBlocking, lo);
        cudaEventCreateWithFlags(&ev_fork, cudaEventDisableTiming);
        cudaEventCreateWithFlags(&ev_scan_done, cudaEventDisableTiming);
        inited = 1;
    }

    // fork: persistent small-grid scan co-resides with prep + GEMMs
    cudaEventRecord(ev_fork, 0);
    cudaStreamWaitEvent(s_scan, ev_fork, 0);
    scan_kernel<<<SCAN_BLOCKS, 256, 0, s_scan>>>(A);
    cudaEventRecord(ev_scan_done, s_scan);

    prep_kernel<<<1024, 256>>>(q, k, W1[0], W1[1], W1[2], W2[0], W2[1], W2[2]);

    dim3 gg(FDIM / 64, NROWS / 64, 3);   // (4, 128, 3) = 1536 blocks
    gemm_l1<<<gg, 256, SMEM_GEMM>>>(B1[0], B1[1], B1[2]);
    gemm_l2<<<gg, 256, SMEM_GEMM>>>(B2[0], B2[1], B2[2]);

    // join: attn2 needs scan results + embeddings
    cudaStreamWaitEvent(0, ev_scan_done, 0);
    attn2_kernel<<<NROWS, 256>>>(GM[0], BT[0], GM[1], BT[1], GM[2], BT[2],
                                 (float*)d_out);
}

// round 12
// speedup vs baseline: 1.1163x; 1.1163x over previous
#include <cuda_runtime.h>
#include <cuda_bf16.h>
#include <cstdint>
#include <math.h>

#define NROWS 8192
#define FDIM  256
#define EPS   1e-5f
#define SLOPE 0.01f
#define MAXD  128

typedef __nv_bfloat16 bf16;

// -------- scratch (device globals) --------
__device__ bf16  g_x_hi[2][NROWS * 128];
__device__ bf16  g_x_lo[2][NROWS * 128];
__device__ bf16  g_w1t_hi[3][FDIM * 128];
__device__ bf16  g_w1t_lo[3][FDIM * 128];
__device__ bf16  g_w2t_hi[3][FDIM * FDIM];
__device__ bf16  g_w2t_lo[3][FDIM * FDIM];
__device__ bf16  g_h1_hi[3][NROWS * FDIM];
__device__ bf16  g_h1_lo[3][NROWS * FDIM];
__device__ float g_h2[3][NROWS * FDIM];
__device__ float g_sum[3][FDIM];
__device__ float g_sumsq[3][FDIM];
__device__ int   g_deg[NROWS];
__device__ int   g_nbr[NROWS * MAXD];

#define MMA_BF16(d, a, b) \
    asm volatile("mma.sync.aligned.m16n8k16.row.col.f32.bf16.bf16.f32 " \
                 "{%0,%1,%2,%3}, {%4,%5,%6,%7}, {%8,%9}, {%0,%1,%2,%3};" \
                 : "+f"(d[0]), "+f"(d[1]), "+f"(d[2]), "+f"(d[3]) \
                 : "r"(a[0]), "r"(a[1]), "r"(a[2]), "r"(a[3]), "r"(b[0]), "r"(b[1]))

#define LDSM4(r, a) \
    asm volatile("ldmatrix.sync.aligned.m8n8.x4.shared.b16 {%0,%1,%2,%3}, [%4];" \
                 : "=r"((r)[0]), "=r"((r)[1]), "=r"((r)[2]), "=r"((r)[3]) : "r"(a))

__device__ __forceinline__ unsigned smem_u32(const void* p) {
    return (unsigned)__cvta_generic_to_shared(p);
}
#define CP16(dst, src) \
    asm volatile("cp.async.cg.shared.global [%0], [%1], 16;" :: "r"(dst), "l"(src))

// stage: A hi/lo 64x40, B hi/lo 64x40 (bf16) = 10240 elems = 20KB
#define ST_ELEMS 10240
#define OFF_AH 0
#define OFF_AL 2560
#define OFF_BH 5120
#define OFF_BL 7680

extern __shared__ bf16 dsm[];

// -------- fused scan + prep: CSR build + input/weight split, one kernel --------
__global__ __launch_bounds__(256) void scan_prep_kernel(
    const float* __restrict__ A,
    const float* __restrict__ q, const float* __restrict__ k,
    const float* __restrict__ w1q, const float* __restrict__ w1k,
    const float* __restrict__ w1v,
    const float* __restrict__ w2q, const float* __restrict__ w2k,
    const float* __restrict__ w2v)
{
    const int tid = threadIdx.x;
    const int lane = tid & 31, wid = tid >> 5;

    // ---- prep part (grid-stride over all 8192 blocks) ----
    {
        const int idx = blockIdx.x * 256 + tid;
        const int stride = gridDim.x * 256;
        const int NX = NROWS * 128;

        for (int i = idx; i < 3 * FDIM; i += stride) {
            ((float*)g_sum)[i] = 0.f;
            ((float*)g_sumsq)[i] = 0.f;
        }
        for (int i = idx; i < NX; i += stride) {
            float v = q[i];
            bf16 h = __float2bfloat16(v);
            g_x_hi[0][i] = h;
            g_x_lo[0][i] = __float2bfloat16(v - __bfloat162float(h));
            float v2 = k[i];
            bf16 h2 = __float2bfloat16(v2);
            g_x_hi[1][i] = h2;
            g_x_lo[1][i] = __float2bfloat16(v2 - __bfloat162float(h2));
        }
        const float* W1[3] = { w1q, w1k, w1v };
        for (int p = 0; p < 3; ++p) {
            const float* w = W1[p];
            for (int i = idx; i < 128 * FDIM; i += stride) {
                int kk = i / FDIM, n = i % FDIM;
                float v = w[i];
                bf16 h = __float2bfloat16(v);
                g_w1t_hi[p][n * 128 + kk] = h;
                g_w1t_lo[p][n * 128 + kk] = __float2bfloat16(v - __bfloat162float(h));
            }
        }
        const float* W2[3] = { w2q, w2k, w2v };
        for (int p = 0; p < 3; ++p) {
            const float* w = W2[p];
            for (int i = idx; i < FDIM * FDIM; i += stride) {
                int kk = i / FDIM, n = i % FDIM;
                float v = w[i];
                bf16 h = __float2bfloat16(v);
                g_w2t_hi[p][n * FDIM + kk] = h;
                g_w2t_lo[p][n * FDIM + kk] = __float2bfloat16(v - __bfloat162float(h));
            }
        }
    }

    // ---- scan part: one A row per block ----
    __shared__ int wtot[8];
    const int i = blockIdx.x;
    const float4* arow = (const float4*)(A + (size_t)i * NROWS);
    float4 vals[8];
    int cnt = 0;
    #pragma unroll
    for (int it = 0; it < 8; ++it) {
        vals[it] = __ldcs(arow + tid + it * 256);
        cnt += (vals[it].x != 0.f) + (vals[it].y != 0.f) +
               (vals[it].z != 0.f) + (vals[it].w != 0.f);
    }

    int incl = cnt;
    #pragma unroll
    for (int o = 1; o < 32; o <<= 1) {
        int v = __shfl_up_sync(0xffffffffu, incl, o);
        if (lane >= o) incl += v;
    }
    if (lane == 31) wtot[wid] = incl;
    __syncthreads();
    int base = 0, total = 0;
    #pragma unroll
    for (int w = 0; w < 8; ++w) {
        int t = wtot[w];
        if (w < wid) base += t;
        total += t;
    }
    int pos = base + incl - cnt;
    int* nb = g_nbr + (size_t)i * MAXD;
    #pragma unroll
    for (int it = 0; it < 8; ++it) {
        int b4 = (tid + it * 256) * 4;
        if (vals[it].x != 0.f) { if (pos < MAXD) nb[pos] = b4 + 0; pos++; }
        if (vals[it].y != 0.f) { if (pos < MAXD) nb[pos] = b4 + 1; pos++; }
        if (vals[it].z != 0.f) { if (pos < MAXD) nb[pos] = b4 + 2; pos++; }
        if (vals[it].w != 0.f) { if (pos < MAXD) nb[pos] = b4 + 3; pos++; }
    }
    if (tid == 0) g_deg[i] = (total > MAXD) ? MAXD : total;
}

// -------- GEMM core: TM=64, TN=64, 8 warps (2m x 4n), warp 32x16; K templated --------
template<int STATS, int K>
__device__ __forceinline__ void gemm_core(
    const bf16* __restrict__ Ahi, const bf16* __restrict__ Alo,
    const bf16* __restrict__ Bhi, const bf16* __restrict__ Blo,
    const float* __restrict__ bias,
    bf16* __restrict__ OutHi, bf16* __restrict__ OutLo,
    float* __restrict__ OutF, float* __restrict__ gsum, float* __restrict__ gsq)
{
    const int tid  = threadIdx.x;
    const int lane = tid & 31, wid = tid >> 5;
    const int g = lane >> 2, tg = lane & 3;
    const int wm = (wid >> 2) * 32;
    const int wn = (wid & 3) * 16;
    const int bm = blockIdx.y * 64, bn = blockIdx.x * 64;

    const int r_ld  = tid >> 2;
    const int cg_ld = (tid & 3) * 8;

    const unsigned offA = (unsigned)(((lane & 7) + ((lane >> 3) & 1) * 8) * 40 + (lane >> 4) * 8);
    const unsigned offB = (unsigned)(((lane & 7) + (lane >> 4) * 8) * 40 + ((lane >> 3) & 1) * 8);

    float acc[2][2][4];
    #pragma unroll
    for (int mt = 0; mt < 2; ++mt)
        #pragma unroll
        for (int nt = 0; nt < 2; ++nt)
            #pragma unroll
            for (int c = 0; c < 4; ++c) acc[mt][nt][c] = 0.f;

    constexpr int nchunks = K >> 5;

    auto load_stage = [&](int st, int k0) {
        bf16* base = dsm + st * ST_ELEMS;
        CP16(smem_u32(base + OFF_AH + r_ld * 40 + cg_ld),
             Ahi + (size_t)(bm + r_ld) * K + k0 + cg_ld);
        CP16(smem_u32(base + OFF_AL + r_ld * 40 + cg_ld),
             Alo + (size_t)(bm + r_ld) * K + k0 + cg_ld);
        CP16(smem_u32(base + OFF_BH + r_ld * 40 + cg_ld),
             Bhi + (size_t)(bn + r_ld) * K + k0 + cg_ld);
        CP16(smem_u32(base + OFF_BL + r_ld * 40 + cg_ld),
             Blo + (size_t)(bn + r_ld) * K + k0 + cg_ld);
        asm volatile("cp.async.commit_group;");
    };

    load_stage(0, 0);

    #pragma unroll
    for (int c = 0; c < nchunks; ++c) {
        const int cur = c & 1;
        if (c + 1 < nchunks) {
            load_stage(cur ^ 1, (c + 1) * 32);
            asm volatile("cp.async.wait_group 1;");
        } else {
            asm volatile("cp.async.wait_group 0;");
        }
        __syncthreads();

        const unsigned sb = smem_u32(dsm + cur * ST_ELEMS);
        const unsigned aAh = sb + (OFF_AH + offA) * 2;
        const unsigned aAl = sb + (OFF_AL + offA) * 2;
        const unsigned aBh = sb + (OFF_BH + offB) * 2;
        const unsigned aBl = sb + (OFF_BL + offB) * 2;

        #pragma unroll
        for (int ks = 0; ks < 2; ++ks) {
            const unsigned kb2 = (unsigned)(ks * 16) * 2;
            unsigned int ah[2][4], al[2][4], bf[4];
            const unsigned tom0 = (unsigned)(wm * 40) * 2 + kb2;
            const unsigned tom1 = (unsigned)((wm + 16) * 40) * 2 + kb2;
            const unsigned ton  = (unsigned)(wn * 40) * 2 + kb2;
            LDSM4(ah[0], aAh + tom0);
            LDSM4(ah[1], aAh + tom1);
            LDSM4(al[0], aAl + tom0);
            LDSM4(al[1], aAl + tom1);
            LDSM4(bf, aBh + ton);
            #pragma unroll
            for (int mt = 0; mt < 2; ++mt) {
                MMA_BF16(acc[mt][0], ah[mt], (&bf[0]));
                MMA_BF16(acc[mt][1], ah[mt], (&bf[2]));
            }
            #pragma unroll
            for (int mt = 0; mt < 2; ++mt) {
                MMA_BF16(acc[mt][0], al[mt], (&bf[0]));
                MMA_BF16(acc[mt][1], al[mt], (&bf[2]));
            }
            LDSM4(bf, aBl + ton);
            #pragma unroll
            for (int mt = 0; mt < 2; ++mt) {
                MMA_BF16(acc[mt][0], ah[mt], (&bf[0]));
                MMA_BF16(acc[mt][1], ah[mt], (&bf[2]));
            }
        }
        __syncthreads();
    }

    float hv[2][2][4];
    #pragma unroll
    for (int mt = 0; mt < 2; ++mt)
        #pragma unroll
        for (int nt = 0; nt < 2; ++nt)
            #pragma unroll
            for (int c = 0; c < 4; ++c) {
                int col = wn + nt * 8 + 2 * tg + (c & 1);
                float v = acc[mt][nt][c] + bias[bn + col];
                hv[mt][nt][c] = (v >= 0.f) ? v : SLOPE * v;
            }

    if (STATS == 0) {
        #pragma unroll
        for (int mt = 0; mt < 2; ++mt)
            #pragma unroll
            for (int nt = 0; nt < 2; ++nt)
                #pragma unroll
                for (int c = 0; c < 4; ++c) {
                    int row = bm + wm + mt * 16 + g + ((c >> 1) ? 8 : 0);
                    int col = bn + wn + nt * 8 + 2 * tg + (c & 1);
                    float v = hv[mt][nt][c];
                    bf16 h = __float2bfloat16(v);
                    size_t idx = (size_t)row * FDIM + col;
                    OutHi[idx] = h;
                    OutLo[idx] = __float2bfloat16(v - __bfloat162float(h));
                }
    } else {
        #pragma unroll
        for (int mt = 0; mt < 2; ++mt)
            #pragma unroll
            for (int nt = 0; nt < 2; ++nt)
                #pragma unroll
                for (int c = 0; c < 4; ++c) {
                    int row = bm + wm + mt * 16 + g + ((c >> 1) ? 8 : 0);
                    int col = bn + wn + nt * 8 + 2 * tg + (c & 1);
                    OutF[(size_t)row * FDIM + col] = hv[mt][nt][c];
                }
        float* csum = (float*)dsm;
        float* csq  = csum + 64;
        if (tid < 128) ((float*)dsm)[tid] = 0.f;
        __syncthreads();
        #pragma unroll
        for (int nt = 0; nt < 2; ++nt)
            #pragma unroll
            for (int p = 0; p < 2; ++p) {
                int col = wn + nt * 8 + 2 * tg + p;
                float a = hv[0][nt][p], b = hv[0][nt][p + 2];
                float c2 = hv[1][nt][p], d = hv[1][nt][p + 2];
                atomicAdd(&csum[col], a + b + c2 + d);
                atomicAdd(&csq[col], a * a + b * b + c2 * c2 + d * d);
            }
        __syncthreads();
        if (tid < 64) {
            atomicAdd(&gsum[bn + tid], csum[tid]);
            atomicAdd(&gsq[bn + tid], csq[tid]);
        }
    }
}

__global__ __launch_bounds__(256, 4) void gemm_l1(const float* __restrict__ b1q,
                                                  const float* __restrict__ b1k,
                                                  const float* __restrict__ b1v)
{
    const int p = blockIdx.z;
    const int xi = (p == 0) ? 0 : 1;
    const float* bias = (p == 0) ? b1q : ((p == 1) ? b1k : b1v);
    gemm_core<0, 128>(g_x_hi[xi], g_x_lo[xi], g_w1t_hi[p], g_w1t_lo[p], bias,
                      g_h1_hi[p], g_h1_lo[p], nullptr, nullptr, nullptr);
}

__global__ __launch_bounds__(256, 4) void gemm_l2(const float* __restrict__ b2q,
                                                  const float* __restrict__ b2k,
                                                  const float* __restrict__ b2v)
{
    const int p = blockIdx.z;
    const float* bias = (p == 0) ? b2q : ((p == 1) ? b2k : b2v);
    gemm_core<1, 256>(g_h1_hi[p], g_h1_lo[p], g_w2t_hi[p], g_w2t_lo[p], bias,
                      nullptr, nullptr, g_h2[p], g_sum[p], g_sumsq[p]);
}

// -------- attention compute on CSR (no A access) --------
__global__ __launch_bounds__(256) void attn2_kernel(
    const float* __restrict__ gq, const float* __restrict__ bq,
    const float* __restrict__ gk, const float* __restrict__ bk,
    const float* __restrict__ gv, const float* __restrict__ bv,
    float* __restrict__ out)
{
    const int i = blockIdx.x;
    const int tid = threadIdx.x;
    const int lane = tid & 31, wid = tid >> 5;

    __shared__ float qs[FDIM];
    __shared__ int   snbr[MAXD];
    __shared__ float ez[MAXD];
    __shared__ float red[8];
    __shared__ float s_se, s_cst;

    const int total = g_deg[i];
    if (tid < total) snbr[tid] = g_nbr[(size_t)i * MAXD + tid];

    const float inv = 1.0f / NROWS;
    float m0 = g_sum[0][tid] * inv, v0 = g_sumsq[0][tid] * inv - m0 * m0;
    float sq_ = gq[tid] * rsqrtf(v0 + EPS), shq_ = bq[tid] - m0 * sq_;
    float m1 = g_sum[1][tid] * inv, v1 = g_sumsq[1][tid] * inv - m1 * m1;
    float sk_ = gk[tid] * rsqrtf(v1 + EPS), shk_ = bk[tid] - m1 * sk_;
    float m2 = g_sum[2][tid] * inv, v2 = g_sumsq[2][tid] * inv - m2 * m2;
    float sv_ = gv[tid] * rsqrtf(v2 + EPS), shv_ = bv[tid] - m2 * sv_;

    float qn = fmaf(sq_, g_h2[0][(size_t)i * FDIM + tid], shq_);
    qs[tid] = qn * sk_;
    float cpart = qn * shk_;
    #pragma unroll
    for (int o = 16; o; o >>= 1) cpart += __shfl_xor_sync(0xffffffffu, cpart, o);
    if (lane == 0) red[wid] = cpart;
    __syncthreads();
    if (tid == 0) {
        float r = 0.f;
        #pragma unroll
        for (int w = 0; w < 8; ++w) r += red[w];
        s_cst = r;
    }
    __syncthreads();

    const float cst = s_cst;
    const float4* q4 = (const float4*)qs;
    float4 a0 = q4[lane * 2], a1 = q4[lane * 2 + 1];
    const float* Kr = g_h2[1];
    for (int n = wid; n < total; n += 8) {
        const float4* kr = (const float4*)(Kr + (size_t)snbr[n] * FDIM);
        float4 b0 = kr[lane * 2], b1 = kr[lane * 2 + 1];
        float s = a0.x * b0.x + a0.y * b0.y + a0.z * b0.z + a0.w * b0.w
                + a1.x * b1.x + a1.y * b1.y + a1.z * b1.z + a1.w * b1.w;
        #pragma unroll
        for (int o = 16; o; o >>= 1) s += __shfl_xor_sync(0xffffffffu, s, o);
        if (lane == 0) ez[n] = expf((s + cst) * 0.0625f);
    }
    __syncthreads();

    const float* Vr = g_h2[2];
    float num = 0.f, sub = 0.f;
    #pragma unroll 4
    for (int n = 0; n < total; ++n) {
        float v = Vr[(size_t)snbr[n] * FDIM + tid];
        float e = ez[n];
        num = fmaf(e, v, num);
        sub += v;
    }

    float se = 0.f;
    for (int n = tid; n < total; n += 256) se += ez[n];
    #pragma unroll
    for (int o = 16; o; o >>= 1) se += __shfl_xor_sync(0xffffffffu, se, o);
    if (lane == 0) red[wid] = se;
    __syncthreads();
    if (wid == 0) {
        float r = (lane < 8) ? red[lane] : 0.f;
        #pragma unroll
        for (int o = 4; o; o >>= 1) r += __shfl_xor_sync(0xffffffffu, r, o);
        if (lane == 0) s_se = r;
    }
    __syncthreads();
    se = s_se;

    float totalf = (float)total;
    float denom = ((float)NROWS - totalf) + se;
    float o = (NROWS * bv[tid] + sv_ * (num - sub) + shv_ * (se - totalf)) / denom;
    out[(size_t)i * FDIM + tid] = o;
}

// -------- host --------
extern "C" void kernel_launch(void* const* d_in, const int* in_sizes, int n_in,
                              void* d_out, int out_size)
{
    const float* A = (const float*)d_in[0];
    const float* q = (const float*)d_in[1];
    const float* k = (const float*)d_in[2];
    const float* W1[3] = { (const float*)d_in[3],  (const float*)d_in[9],  (const float*)d_in[15] };
    const float* B1[3] = { (const float*)d_in[4],  (const float*)d_in[10], (const float*)d_in[16] };
    const float* W2[3] = { (const float*)d_in[5],  (const float*)d_in[11], (const float*)d_in[17] };
    const float* B2[3] = { (const float*)d_in[6],  (const float*)d_in[12], (const float*)d_in[18] };
    const float* GM[3] = { (const float*)d_in[7],  (const float*)d_in[13], (const float*)d_in[19] };
    const float* BT[3] = { (const float*)d_in[8],  (const float*)d_in[14], (const float*)d_in[20] };

    static int smem_set = 0;
    const int SMEM_GEMM = 2 * ST_ELEMS * (int)sizeof(bf16);   // 40960
    if (!smem_set) {
        cudaFuncSetAttribute(gemm_l1, cudaFuncAttributeMaxDynamicSharedMemorySize, SMEM_GEMM);
        cudaFuncSetAttribute(gemm_l2, cudaFuncAttributeMaxDynamicSharedMemorySize, SMEM_GEMM);
        smem_set = 1;
    }

    scan_prep_kernel<<<NROWS, 256>>>(A, q, k, W1[0], W1[1], W1[2],
                                     W2[0], W2[1], W2[2]);

    dim3 gg(FDIM / 64, NROWS / 64, 3);   // (4, 128, 3) = 1536 blocks
    gemm_l1<<<gg, 256, SMEM_GEMM>>>(B1[0], B1[1], B1[2]);
    gemm_l2<<<gg, 256, SMEM_GEMM>>>(B2[0], B2[1], B2[2]);

    attn2_kernel<<<NROWS, 256>>>(GM[0], BT[0], GM[1], BT[1], GM[2], BT[2],
                                 (float*)d_out);
}

// round 14
// speedup vs baseline: 1.1237x; 1.0066x over previous
#include <cuda_runtime.h>
#include <cuda_bf16.h>
#include <cstdint>
#include <math.h>

#define NROWS 8192
#define FDIM  256
#define EPS   1e-5f
#define SLOPE 0.01f
#define MAXD  128

typedef __nv_bfloat16 bf16;

// -------- scratch (device globals) --------
__device__ bf16  g_x_hi[2][NROWS * 128];
__device__ bf16  g_x_lo[2][NROWS * 128];
__device__ bf16  g_w1t_hi[3][FDIM * 128];
__device__ bf16  g_w1t_lo[3][FDIM * 128];
__device__ bf16  g_w2t_hi[3][FDIM * FDIM];
__device__ bf16  g_w2t_lo[3][FDIM * FDIM];
__device__ bf16  g_h1_hi[3][NROWS * FDIM];
__device__ bf16  g_h1_lo[3][NROWS * FDIM];
__device__ __align__(16) float g_h2[3][NROWS * FDIM];
__device__ float g_sum[3][FDIM];
__device__ float g_sumsq[3][FDIM];
__device__ int   g_deg[NROWS];
__device__ int   g_nbr[NROWS * MAXD];

#define MMA_BF16(d, a, b) \
    asm volatile("mma.sync.aligned.m16n8k16.row.col.f32.bf16.bf16.f32 " \
                 "{%0,%1,%2,%3}, {%4,%5,%6,%7}, {%8,%9}, {%0,%1,%2,%3};" \
                 : "+f"(d[0]), "+f"(d[1]), "+f"(d[2]), "+f"(d[3]) \
                 : "r"(a[0]), "r"(a[1]), "r"(a[2]), "r"(a[3]), "r"(b[0]), "r"(b[1]))

#define LDSM4(r, a) \
    asm volatile("ldmatrix.sync.aligned.m8n8.x4.shared.b16 {%0,%1,%2,%3}, [%4];" \
                 : "=r"((r)[0]), "=r"((r)[1]), "=r"((r)[2]), "=r"((r)[3]) : "r"(a))

__device__ __forceinline__ unsigned smem_u32(const void* p) {
    return (unsigned)__cvta_generic_to_shared(p);
}
#define CP16(dst, src) \
    asm volatile("cp.async.cg.shared.global [%0], [%1], 16;" :: "r"(dst), "l"(src))

// stage: A hi/lo 64x40, B hi/lo 64x40 (bf16) = 10240 elems = 20KB
#define ST_ELEMS 10240
#define OFF_AH 0
#define OFF_AL 2560
#define OFF_BH 5120
#define OFF_BL 7680

extern __shared__ bf16 dsm[];

// -------- fused scan + prep: CSR build + input/weight split, one kernel --------
__global__ __launch_bounds__(256) void scan_prep_kernel(
    const float* __restrict__ A,
    const float* __restrict__ q, const float* __restrict__ k,
    const float* __restrict__ w1q, const float* __restrict__ w1k,
    const float* __restrict__ w1v,
    const float* __restrict__ w2q, const float* __restrict__ w2k,
    const float* __restrict__ w2v)
{
    const int tid = threadIdx.x;
    const int lane = tid & 31, wid = tid >> 5;

    // ---- prep part (grid-stride over all 8192 blocks) ----
    {
        const int idx = blockIdx.x * 256 + tid;
        const int stride = gridDim.x * 256;
        const int NX = NROWS * 128;

        for (int i = idx; i < 3 * FDIM; i += stride) {
            ((float*)g_sum)[i] = 0.f;
            ((float*)g_sumsq)[i] = 0.f;
        }
        for (int i = idx; i < NX; i += stride) {
            float v = q[i];
            bf16 h = __float2bfloat16(v);
            g_x_hi[0][i] = h;
            g_x_lo[0][i] = __float2bfloat16(v - __bfloat162float(h));
            float v2 = k[i];
            bf16 h2 = __float2bfloat16(v2);
            g_x_hi[1][i] = h2;
            g_x_lo[1][i] = __float2bfloat16(v2 - __bfloat162float(h2));
        }
        const float* W1[3] = { w1q, w1k, w1v };
        for (int p = 0; p < 3; ++p) {
            const float* w = W1[p];
            for (int i = idx; i < 128 * FDIM; i += stride) {
                int kk = i / FDIM, n = i % FDIM;
                float v = w[i];
                bf16 h = __float2bfloat16(v);
                g_w1t_hi[p][n * 128 + kk] = h;
                g_w1t_lo[p][n * 128 + kk] = __float2bfloat16(v - __bfloat162float(h));
            }
        }
        const float* W2[3] = { w2q, w2k, w2v };
        for (int p = 0; p < 3; ++p) {
            const float* w = W2[p];
            for (int i = idx; i < FDIM * FDIM; i += stride) {
                int kk = i / FDIM, n = i % FDIM;
                float v = w[i];
                bf16 h = __float2bfloat16(v);
                g_w2t_hi[p][n * FDIM + kk] = h;
                g_w2t_lo[p][n * FDIM + kk] = __float2bfloat16(v - __bfloat162float(h));
            }
        }
    }

    // ---- scan part: one A row per block ----
    __shared__ int wtot[8];
    const int i = blockIdx.x;
    const float4* arow = (const float4*)(A + (size_t)i * NROWS);
    float4 vals[8];
    int cnt = 0;
    #pragma unroll
    for (int it = 0; it < 8; ++it) {
        vals[it] = __ldcs(arow + tid + it * 256);
        cnt += (vals[it].x != 0.f) + (vals[it].y != 0.f) +
               (vals[it].z != 0.f) + (vals[it].w != 0.f);
    }

    int incl = cnt;
    #pragma unroll
    for (int o = 1; o < 32; o <<= 1) {
        int v = __shfl_up_sync(0xffffffffu, incl, o);
        if (lane >= o) incl += v;
    }
    if (lane == 31) wtot[wid] = incl;
    __syncthreads();
    int base = 0, total = 0;
    #pragma unroll
    for (int w = 0; w < 8; ++w) {
        int t = wtot[w];
        if (w < wid) base += t;
        total += t;
    }
    int pos = base + incl - cnt;
    int* nb = g_nbr + (size_t)i * MAXD;
    #pragma unroll
    for (int it = 0; it < 8; ++it) {
        int b4 = (tid + it * 256) * 4;
        if (vals[it].x != 0.f) { if (pos < MAXD) nb[pos] = b4 + 0; pos++; }
        if (vals[it].y != 0.f) { if (pos < MAXD) nb[pos] = b4 + 1; pos++; }
        if (vals[it].z != 0.f) { if (pos < MAXD) nb[pos] = b4 + 2; pos++; }
        if (vals[it].w != 0.f) { if (pos < MAXD) nb[pos] = b4 + 3; pos++; }
    }
    if (tid == 0) g_deg[i] = (total > MAXD) ? MAXD : total;
}

// -------- GEMM core: TM=64, TN=64, 8 warps (2m x 4n), warp 32x16; K templated --------
template<int STATS, int K>
__device__ __forceinline__ void gemm_core(
    const bf16* __restrict__ Ahi, const bf16* __restrict__ Alo,
    const bf16* __restrict__ Bhi, const bf16* __restrict__ Blo,
    const float* __restrict__ bias,
    bf16* __restrict__ OutHi, bf16* __restrict__ OutLo,
    float* __restrict__ OutF, float* __restrict__ gsum, float* __restrict__ gsq)
{
    const int tid  = threadIdx.x;
    const int lane = tid & 31, wid = tid >> 5;
    const int g = lane >> 2, tg = lane & 3;
    const int wm = (wid >> 2) * 32;
    const int wn = (wid & 3) * 16;
    const int bm = blockIdx.y * 64, bn = blockIdx.x * 64;

    const int r_ld  = tid >> 2;
    const int cg_ld = (tid & 3) * 8;

    const unsigned offA = (unsigned)(((lane & 7) + ((lane >> 3) & 1) * 8) * 40 + (lane >> 4) * 8);
    const unsigned offB = (unsigned)(((lane & 7) + (lane >> 4) * 8) * 40 + ((lane >> 3) & 1) * 8);

    float acc[2][2][4];
    #pragma unroll
    for (int mt = 0; mt < 2; ++mt)
        #pragma unroll
        for (int nt = 0; nt < 2; ++nt)
            #pragma unroll
            for (int c = 0; c < 4; ++c) acc[mt][nt][c] = 0.f;

    constexpr int nchunks = K >> 5;

    auto load_stage = [&](int st, int k0) {
        bf16* base = dsm + st * ST_ELEMS;
        CP16(smem_u32(base + OFF_AH + r_ld * 40 + cg_ld),
             Ahi + (size_t)(bm + r_ld) * K + k0 + cg_ld);
        CP16(smem_u32(base + OFF_AL + r_ld * 40 + cg_ld),
             Alo + (size_t)(bm + r_ld) * K + k0 + cg_ld);
        CP16(smem_u32(base + OFF_BH + r_ld * 40 + cg_ld),
             Bhi + (size_t)(bn + r_ld) * K + k0 + cg_ld);
        CP16(smem_u32(base + OFF_BL + r_ld * 40 + cg_ld),
             Blo + (size_t)(bn + r_ld) * K + k0 + cg_ld);
        asm volatile("cp.async.commit_group;");
    };

    load_stage(0, 0);

    #pragma unroll
    for (int c = 0; c < nchunks; ++c) {
        const int cur = c & 1;
        if (c + 1 < nchunks) {
            load_stage(cur ^ 1, (c + 1) * 32);
            asm volatile("cp.async.wait_group 1;");
        } else {
            asm volatile("cp.async.wait_group 0;");
        }
        __syncthreads();

        const unsigned sb = smem_u32(dsm + cur * ST_ELEMS);
        const unsigned aAh = sb + (OFF_AH + offA) * 2;
        const unsigned aAl = sb + (OFF_AL + offA) * 2;
        const unsigned aBh = sb + (OFF_BH + offB) * 2;
        const unsigned aBl = sb + (OFF_BL + offB) * 2;

        #pragma unroll
        for (int ks = 0; ks < 2; ++ks) {
            const unsigned kb2 = (unsigned)(ks * 16) * 2;
            unsigned int ah[2][4], al[2][4], bf[4];
            const unsigned tom0 = (unsigned)(wm * 40) * 2 + kb2;
            const unsigned tom1 = (unsigned)((wm + 16) * 40) * 2 + kb2;
            const unsigned ton  = (unsigned)(wn * 40) * 2 + kb2;
            LDSM4(ah[0], aAh + tom0);
            LDSM4(ah[1], aAh + tom1);
            LDSM4(al[0], aAl + tom0);
            LDSM4(al[1], aAl + tom1);
            LDSM4(bf, aBh + ton);
            #pragma unroll
            for (int mt = 0; mt < 2; ++mt) {
                MMA_BF16(acc[mt][0], ah[mt], (&bf[0]));
                MMA_BF16(acc[mt][1], ah[mt], (&bf[2]));
            }
            #pragma unroll
            for (int mt = 0; mt < 2; ++mt) {
                MMA_BF16(acc[mt][0], al[mt], (&bf[0]));
                MMA_BF16(acc[mt][1], al[mt], (&bf[2]));
            }
            LDSM4(bf, aBl + ton);
            #pragma unroll
            for (int mt = 0; mt < 2; ++mt) {
                MMA_BF16(acc[mt][0], ah[mt], (&bf[0]));
                MMA_BF16(acc[mt][1], ah[mt], (&bf[2]));
            }
        }
        __syncthreads();
    }

    float hv[2][2][4];
    #pragma unroll
    for (int mt = 0; mt < 2; ++mt)
        #pragma unroll
        for (int nt = 0; nt < 2; ++nt)
            #pragma unroll
            for (int c = 0; c < 4; ++c) {
                int col = wn + nt * 8 + 2 * tg + (c & 1);
                float v = acc[mt][nt][c] + bias[bn + col];
                hv[mt][nt][c] = (v >= 0.f) ? v : SLOPE * v;
            }

    if (STATS == 0) {
        #pragma unroll
        for (int mt = 0; mt < 2; ++mt)
            #pragma unroll
            for (int nt = 0; nt < 2; ++nt)
                #pragma unroll
                for (int c = 0; c < 4; ++c) {
                    int row = bm + wm + mt * 16 + g + ((c >> 1) ? 8 : 0);
                    int col = bn + wn + nt * 8 + 2 * tg + (c & 1);
                    float v = hv[mt][nt][c];
                    bf16 h = __float2bfloat16(v);
                    size_t idx = (size_t)row * FDIM + col;
                    OutHi[idx] = h;
                    OutLo[idx] = __float2bfloat16(v - __bfloat162float(h));
                }
    } else {
        #pragma unroll
        for (int mt = 0; mt < 2; ++mt)
            #pragma unroll
            for (int nt = 0; nt < 2; ++nt)
                #pragma unroll
                for (int c = 0; c < 4; ++c) {
                    int row = bm + wm + mt * 16 + g + ((c >> 1) ? 8 : 0);
                    int col = bn + wn + nt * 8 + 2 * tg + (c & 1);
                    OutF[(size_t)row * FDIM + col] = hv[mt][nt][c];
                }
        float* csum = (float*)dsm;
        float* csq  = csum + 64;
        if (tid < 128) ((float*)dsm)[tid] = 0.f;
        __syncthreads();
        #pragma unroll
        for (int nt = 0; nt < 2; ++nt)
            #pragma unroll
            for (int p = 0; p < 2; ++p) {
                int col = wn + nt * 8 + 2 * tg + p;
                float a = hv[0][nt][p], b = hv[0][nt][p + 2];
                float c2 = hv[1][nt][p], d = hv[1][nt][p + 2];
                atomicAdd(&csum[col], a + b + c2 + d);
                atomicAdd(&csq[col], a * a + b * b + c2 * c2 + d * d);
            }
        __syncthreads();
        if (tid < 64) {
            atomicAdd(&gsum[bn + tid], csum[tid]);
            atomicAdd(&gsq[bn + tid], csq[tid]);
        }
    }
}

__global__ __launch_bounds__(256, 4) void gemm_l1(const float* __restrict__ b1q,
                                                  const float* __restrict__ b1k,
                                                  const float* __restrict__ b1v)
{
    const int p = blockIdx.z;
    const int xi = (p == 0) ? 0 : 1;
    const float* bias = (p == 0) ? b1q : ((p == 1) ? b1k : b1v);
    gemm_core<0, 128>(g_x_hi[xi], g_x_lo[xi], g_w1t_hi[p], g_w1t_lo[p], bias,
                      g_h1_hi[p], g_h1_lo[p], nullptr, nullptr, nullptr);
}

__global__ __launch_bounds__(256, 4) void gemm_l2(const float* __restrict__ b2q,
                                                  const float* __restrict__ b2k,
                                                  const float* __restrict__ b2v)
{
    const int p = blockIdx.z;
    const float* bias = (p == 0) ? b2q : ((p == 1) ? b2k : b2v);
    gemm_core<1, 256>(g_h1_hi[p], g_h1_lo[p], g_w2t_hi[p], g_w2t_lo[p], bias,
                      nullptr, nullptr, g_h2[p], g_sum[p], g_sumsq[p]);
}

// -------- attention compute on CSR (vectorized gather) --------
__global__ __launch_bounds__(256) void attn2_kernel(
    const float* __restrict__ gq, const float* __restrict__ bq,
    const float* __restrict__ gk, const float* __restrict__ bk,
    const float* __restrict__ gv, const float* __restrict__ bv,
    float* __restrict__ out)
{
    const int i = blockIdx.x;
    const int tid = threadIdx.x;
    const int lane = tid & 31, wid = tid >> 5;

    __shared__ __align__(16) float qs[FDIM];
    __shared__ __align__(16) float pnum[4][FDIM];
    __shared__ __align__(16) float psub[4][FDIM];
    __shared__ int   snbr[MAXD];
    __shared__ float ez[MAXD];
    __shared__ float red[8];
    __shared__ float s_se, s_cst;

    const int total = g_deg[i];
    if (tid < total) snbr[tid] = g_nbr[(size_t)i * MAXD + tid];

    const float inv = 1.0f / NROWS;
    float m0 = g_sum[0][tid] * inv, v0 = g_sumsq[0][tid] * inv - m0 * m0;
    float sq_ = gq[tid] * rsqrtf(v0 + EPS), shq_ = bq[tid] - m0 * sq_;
    float m1 = g_sum[1][tid] * inv, v1 = g_sumsq[1][tid] * inv - m1 * m1;
    float sk_ = gk[tid] * rsqrtf(v1 + EPS), shk_ = bk[tid] - m1 * sk_;
    float m2 = g_sum[2][tid] * inv, v2 = g_sumsq[2][tid] * inv - m2 * m2;
    float sv_ = gv[tid] * rsqrtf(v2 + EPS), shv_ = bv[tid] - m2 * sv_;

    float qn = fmaf(sq_, g_h2[0][(size_t)i * FDIM + tid], shq_);
    qs[tid] = qn * sk_;
    float cpart = qn * shk_;
    #pragma unroll
    for (int o = 16; o; o >>= 1) cpart += __shfl_xor_sync(0xffffffffu, cpart, o);
    if (lane == 0) red[wid] = cpart;
    __syncthreads();
    if (tid == 0) {
        float r = 0.f;
        #pragma unroll
        for (int w = 0; w < 8; ++w) r += red[w];
        s_cst = r;
    }
    __syncthreads();

    // K-dot products: warps partition neighbors
    const float cst = s_cst;
    const float4* q4 = (const float4*)qs;
    float4 a0 = q4[lane * 2], a1 = q4[lane * 2 + 1];
    const float* Kr = g_h2[1];
    for (int n = wid; n < total; n += 8) {
        const float4* kr = (const float4*)(Kr + (size_t)snbr[n] * FDIM);
        float4 b0 = kr[lane * 2], b1 = kr[lane * 2 + 1];
        float s = a0.x * b0.x + a0.y * b0.y + a0.z * b0.z + a0.w * b0.w
                + a1.x * b1.x + a1.y * b1.y + a1.z * b1.z + a1.w * b1.w;
        #pragma unroll
        for (int o = 16; o; o >>= 1) s += __shfl_xor_sync(0xffffffffu, s, o);
        if (lane == 0) ez[n] = expf((s + cst) * 0.0625f);
    }
    __syncthreads();

    // V accumulation: 4 groups of 64 threads; group grp handles rows n % 4 == grp.
    // Each thread covers 4 features via float4 -> 4x fewer load instructions.
    const int grp = wid >> 1;            // 0..3
    const int t64 = tid & 63;            // 0..63
    const float* Vr = g_h2[2];
    float4 num4 = {0.f, 0.f, 0.f, 0.f};
    float4 sub4 = {0.f, 0.f, 0.f, 0.f};
    for (int n = grp; n < total; n += 4) {
        const float4 v = *(const float4*)(Vr + (size_t)snbr[n] * FDIM + t64 * 4);
        const float e = ez[n];
        num4.x = fmaf(e, v.x, num4.x); num4.y = fmaf(e, v.y, num4.y);
        num4.z = fmaf(e, v.z, num4.z); num4.w = fmaf(e, v.w, num4.w);
        sub4.x += v.x; sub4.y += v.y; sub4.z += v.z; sub4.w += v.w;
    }
    *(float4*)&pnum[grp][t64 * 4] = num4;
    *(float4*)&psub[grp][t64 * 4] = sub4;

    // sum of exp (block reduce)
    float se = 0.f;
    for (int n = tid; n < total; n += 256) se += ez[n];
    #pragma unroll
    for (int o = 16; o; o >>= 1) se += __shfl_xor_sync(0xffffffffu, se, o);
    if (lane == 0) red[wid] = se;
    __syncthreads();
    if (wid == 0) {
        float r = (lane < 8) ? red[lane] : 0.f;
        #pragma unroll
        for (int o = 4; o; o >>= 1) r += __shfl_xor_sync(0xffffffffu, r, o);
        if (lane == 0) s_se = r;
    }
    __syncthreads();
    se = s_se;

    float num = pnum[0][tid] + pnum[1][tid] + pnum[2][tid] + pnum[3][tid];
    float sub = psub[0][tid] + psub[1][tid] + psub[2][tid] + psub[3][tid];

    float totalf = (float)total;
    float denom = ((float)NROWS - totalf) + se;
    float o = (NROWS * bv[tid] + sv_ * (num - sub) + shv_ * (se - totalf)) / denom;
    out[(size_t)i * FDIM + tid] = o;
}

// -------- host --------
extern "C" void kernel_launch(void* const* d_in, const int* in_sizes, int n_in,
                              void* d_out, int out_size)
{
    const float* A = (const float*)d_in[0];
    const float* q = (const float*)d_in[1];
    const float* k = (const float*)d_in[2];
    const float* W1[3] = { (const float*)d_in[3],  (const float*)d_in[9],  (const float*)d_in[15] };
    const float* B1[3] = { (const float*)d_in[4],  (const float*)d_in[10], (const float*)d_in[16] };
    const float* W2[3] = { (const float*)d_in[5],  (const float*)d_in[11], (const float*)d_in[17] };
    const float* B2[3] = { (const float*)d_in[6],  (const float*)d_in[12], (const float*)d_in[18] };
    const float* GM[3] = { (const float*)d_in[7],  (const float*)d_in[13], (const float*)d_in[19] };
    const float* BT[3] = { (const float*)d_in[8],  (const float*)d_in[14], (const float*)d_in[20] };

    static int smem_set = 0;
    const int SMEM_GEMM = 2 * ST_ELEMS * (int)sizeof(bf16);   // 40960
    if (!smem_set) {
        cudaFuncSetAttribute(gemm_l1, cudaFuncAttributeMaxDynamicSharedMemorySize, SMEM_GEMM);
        cudaFuncSetAttribute(gemm_l2, cudaFuncAttributeMaxDynamicSharedMemorySize, SMEM_GEMM);
        smem_set = 1;
    }

    scan_prep_kernel<<<NROWS, 256>>>(A, q, k, W1[0], W1[1], W1[2],
                                     W2[0], W2[1], W2[2]);

    dim3 gg(FDIM / 64, NROWS / 64, 3);   // (4, 128, 3) = 1536 blocks
    gemm_l1<<<gg, 256, SMEM_GEMM>>>(B1[0], B1[1], B1[2]);
    gemm_l2<<<gg, 256, SMEM_GEMM>>>(B2[0], B2[1], B2[2]);

    attn2_kernel<<<NROWS, 256>>>(GM[0], BT[0], GM[1], BT[1], GM[2], BT[2],
                                 (float*)d_out);
}

// round 15
// speedup vs baseline: 1.1556x; 1.0284x over previous
#include <cuda_runtime.h>
#include <cuda_fp16.h>
#include <cstdint>
#include <math.h>

#define NROWS 8192
#define FDIM  256
#define EPS   1e-5f
#define SLOPE 0.01f
#define MAXD  128

typedef __half f16;

// -------- scratch (device globals) --------
__device__ f16   g_x_hi[2][NROWS * 128];
__device__ f16   g_x_lo[2][NROWS * 128];
__device__ f16   g_w1t[3][FDIM * 128];
__device__ f16   g_w2t[3][FDIM * FDIM];
__device__ f16   g_h1_hi[3][NROWS * FDIM];
__device__ f16   g_h1_lo[3][NROWS * FDIM];
__device__ __align__(16) float g_h2[3][NROWS * FDIM];
__device__ float g_sum[3][FDIM];
__device__ float g_sumsq[3][FDIM];
__device__ int   g_deg[NROWS];
__device__ int   g_nbr[NROWS * MAXD];

#define MMA_F16(d, a, b) \
    asm volatile("mma.sync.aligned.m16n8k16.row.col.f32.f16.f16.f32 " \
                 "{%0,%1,%2,%3}, {%4,%5,%6,%7}, {%8,%9}, {%0,%1,%2,%3};" \
                 : "+f"(d[0]), "+f"(d[1]), "+f"(d[2]), "+f"(d[3]) \
                 : "r"(a[0]), "r"(a[1]), "r"(a[2]), "r"(a[3]), "r"(b[0]), "r"(b[1]))

#define LDSM4(r, a) \
    asm volatile("ldmatrix.sync.aligned.m8n8.x4.shared.b16 {%0,%1,%2,%3}, [%4];" \
                 : "=r"((r)[0]), "=r"((r)[1]), "=r"((r)[2]), "=r"((r)[3]) : "r"(a))

__device__ __forceinline__ unsigned smem_u32(const void* p) {
    return (unsigned)__cvta_generic_to_shared(p);
}
#define CP16(dst, src) \
    asm volatile("cp.async.cg.shared.global [%0], [%1], 16;" :: "r"(dst), "l"(src))

// stage: A hi/lo 64x40, B 64x40 (f16) = 7680 elems = 15KB
#define ST_ELEMS 7680
#define OFF_AH 0
#define OFF_AL 2560
#define OFF_BH 5120

extern __shared__ f16 dsm[];

// -------- fused scan + prep: CSR build + input/weight conversion --------
__global__ __launch_bounds__(256) void scan_prep_kernel(
    const float* __restrict__ A,
    const float* __restrict__ q, const float* __restrict__ k,
    const float* __restrict__ w1q, const float* __restrict__ w1k,
    const float* __restrict__ w1v,
    const float* __restrict__ w2q, const float* __restrict__ w2k,
    const float* __restrict__ w2v)
{
    const int tid = threadIdx.x;
    const int lane = tid & 31, wid = tid >> 5;

    // ---- prep part (grid-stride over all 8192 blocks) ----
    {
        const int idx = blockIdx.x * 256 + tid;
        const int stride = gridDim.x * 256;
        const int NX = NROWS * 128;

        for (int i = idx; i < 3 * FDIM; i += stride) {
            ((float*)g_sum)[i] = 0.f;
            ((float*)g_sumsq)[i] = 0.f;
        }
        for (int i = idx; i < NX; i += stride) {
            float v = q[i];
            f16 h = __float2half_rn(v);
            g_x_hi[0][i] = h;
            g_x_lo[0][i] = __float2half_rn(v - __half2float(h));
            float v2 = k[i];
            f16 h2 = __float2half_rn(v2);
            g_x_hi[1][i] = h2;
            g_x_lo[1][i] = __float2half_rn(v2 - __half2float(h2));
        }
        const float* W1[3] = { w1q, w1k, w1v };
        for (int p = 0; p < 3; ++p) {
            const float* w = W1[p];
            for (int i = idx; i < 128 * FDIM; i += stride) {
                int kk = i / FDIM, n = i % FDIM;
                g_w1t[p][n * 128 + kk] = __float2half_rn(w[i]);
            }
        }
        const float* W2[3] = { w2q, w2k, w2v };
        for (int p = 0; p < 3; ++p) {
            const float* w = W2[p];
            for (int i = idx; i < FDIM * FDIM; i += stride) {
                int kk = i / FDIM, n = i % FDIM;
                g_w2t[p][n * FDIM + kk] = __float2half_rn(w[i]);
            }
        }
    }

    // ---- scan part: one A row per block ----
    __shared__ int wtot[8];
    const int i = blockIdx.x;
    const float4* arow = (const float4*)(A + (size_t)i * NROWS);
    float4 vals[8];
    int cnt = 0;
    #pragma unroll
    for (int it = 0; it < 8; ++it) {
        vals[it] = __ldcs(arow + tid + it * 256);
        cnt += (vals[it].x != 0.f) + (vals[it].y != 0.f) +
               (vals[it].z != 0.f) + (vals[it].w != 0.f);
    }

    int incl = cnt;
    #pragma unroll
    for (int o = 1; o < 32; o <<= 1) {
        int v = __shfl_up_sync(0xffffffffu, incl, o);
        if (lane >= o) incl += v;
    }
    if (lane == 31) wtot[wid] = incl;
    __syncthreads();
    int base = 0, total = 0;
    #pragma unroll
    for (int w = 0; w < 8; ++w) {
        int t = wtot[w];
        if (w < wid) base += t;
        total += t;
    }
    int pos = base + incl - cnt;
    int* nb = g_nbr + (size_t)i * MAXD;
    #pragma unroll
    for (int it = 0; it < 8; ++it) {
        int b4 = (tid + it * 256) * 4;
        if (vals[it].x != 0.f) { if (pos < MAXD) nb[pos] = b4 + 0; pos++; }
        if (vals[it].y != 0.f) { if (pos < MAXD) nb[pos] = b4 + 1; pos++; }
        if (vals[it].z != 0.f) { if (pos < MAXD) nb[pos] = b4 + 2; pos++; }
        if (vals[it].w != 0.f) { if (pos < MAXD) nb[pos] = b4 + 3; pos++; }
    }
    if (tid == 0) g_deg[i] = (total > MAXD) ? MAXD : total;
}

// -------- GEMM core: fp16 2-product (hi*w + lo*w); TM=64 TN=64, 8 warps --------
template<int STATS, int K>
__device__ __forceinline__ void gemm_core(
    const f16* __restrict__ Ahi, const f16* __restrict__ Alo,
    const f16* __restrict__ B,
    const float* __restrict__ bias,
    f16* __restrict__ OutHi, f16* __restrict__ OutLo,
    float* __restrict__ OutF, float* __restrict__ gsum, float* __restrict__ gsq)
{
    const int tid  = threadIdx.x;
    const int lane = tid & 31, wid = tid >> 5;
    const int g = lane >> 2, tg = lane & 3;
    const int wm = (wid >> 2) * 32;
    const int wn = (wid & 3) * 16;
    const int bm = blockIdx.y * 64, bn = blockIdx.x * 64;

    const int r_ld  = tid >> 2;
    const int cg_ld = (tid & 3) * 8;

    const unsigned offA = (unsigned)(((lane & 7) + ((lane >> 3) & 1) * 8) * 40 + (lane >> 4) * 8);
    const unsigned offB = (unsigned)(((lane & 7) + (lane >> 4) * 8) * 40 + ((lane >> 3) & 1) * 8);

    float acc[2][2][4];
    #pragma unroll
    for (int mt = 0; mt < 2; ++mt)
        #pragma unroll
        for (int nt = 0; nt < 2; ++nt)
            #pragma unroll
            for (int c = 0; c < 4; ++c) acc[mt][nt][c] = 0.f;

    constexpr int nchunks = K >> 5;

    auto load_stage = [&](int st, int k0) {
        f16* base = dsm + st * ST_ELEMS;
        CP16(smem_u32(base + OFF_AH + r_ld * 40 + cg_ld),
             Ahi + (size_t)(bm + r_ld) * K + k0 + cg_ld);
        CP16(smem_u32(base + OFF_AL + r_ld * 40 + cg_ld),
             Alo + (size_t)(bm + r_ld) * K + k0 + cg_ld);
        CP16(smem_u32(base + OFF_BH + r_ld * 40 + cg_ld),
             B + (size_t)(bn + r_ld) * K + k0 + cg_ld);
        asm volatile("cp.async.commit_group;");
    };

    load_stage(0, 0);

    #pragma unroll
    for (int c = 0; c < nchunks; ++c) {
        const int cur = c & 1;
        if (c + 1 < nchunks) {
            load_stage(cur ^ 1, (c + 1) * 32);
            asm volatile("cp.async.wait_group 1;");
        } else {
            asm volatile("cp.async.wait_group 0;");
        }
        __syncthreads();

        const unsigned sb = smem_u32(dsm + cur * ST_ELEMS);
        const unsigned aAh = sb + (OFF_AH + offA) * 2;
        const unsigned aAl = sb + (OFF_AL + offA) * 2;
        const unsigned aB  = sb + (OFF_BH + offB) * 2;

        #pragma unroll
        for (int ks = 0; ks < 2; ++ks) {
            const unsigned kb2 = (unsigned)(ks * 16) * 2;
            unsigned int ah[2][4], al[2][4], bf[4];
            const unsigned tom0 = (unsigned)(wm * 40) * 2 + kb2;
            const unsigned tom1 = (unsigned)((wm + 16) * 40) * 2 + kb2;
            const unsigned ton  = (unsigned)(wn * 40) * 2 + kb2;
            LDSM4(ah[0], aAh + tom0);
            LDSM4(ah[1], aAh + tom1);
            LDSM4(al[0], aAl + tom0);
            LDSM4(al[1], aAl + tom1);
            LDSM4(bf, aB + ton);
            #pragma unroll
            for (int mt = 0; mt < 2; ++mt) {
                MMA_F16(acc[mt][0], ah[mt], (&bf[0]));
                MMA_F16(acc[mt][1], ah[mt], (&bf[2]));
            }
            #pragma unroll
            for (int mt = 0; mt < 2; ++mt) {
                MMA_F16(acc[mt][0], al[mt], (&bf[0]));
                MMA_F16(acc[mt][1], al[mt], (&bf[2]));
            }
        }
        __syncthreads();
    }

    float hv[2][2][4];
    #pragma unroll
    for (int mt = 0; mt < 2; ++mt)
        #pragma unroll
        for (int nt = 0; nt < 2; ++nt)
            #pragma unroll
            for (int c = 0; c < 4; ++c) {
                int col = wn + nt * 8 + 2 * tg + (c & 1);
                float v = acc[mt][nt][c] + bias[bn + col];
                hv[mt][nt][c] = (v >= 0.f) ? v : SLOPE * v;
            }

    if (STATS == 0) {
        #pragma unroll
        for (int mt = 0; mt < 2; ++mt)
            #pragma unroll
            for (int nt = 0; nt < 2; ++nt)
                #pragma unroll
                for (int c = 0; c < 4; ++c) {
                    int row = bm + wm + mt * 16 + g + ((c >> 1) ? 8 : 0);
                    int col = bn + wn + nt * 8 + 2 * tg + (c & 1);
                    float v = hv[mt][nt][c];
                    f16 h = __float2half_rn(v);
                    size_t idx = (size_t)row * FDIM + col;
                    OutHi[idx] = h;
                    OutLo[idx] = __float2half_rn(v - __half2float(h));
                }
    } else {
        #pragma unroll
        for (int mt = 0; mt < 2; ++mt)
            #pragma unroll
            for (int nt = 0; nt < 2; ++nt)
                #pragma unroll
                for (int c = 0; c < 4; ++c) {
                    int row = bm + wm + mt * 16 + g + ((c >> 1) ? 8 : 0);
                    int col = bn + wn + nt * 8 + 2 * tg + (c & 1);
                    OutF[(size_t)row * FDIM + col] = hv[mt][nt][c];
                }
        float* csum = (float*)dsm;
        float* csq  = csum + 64;
        if (tid < 128) ((float*)dsm)[tid] = 0.f;
        __syncthreads();
        #pragma unroll
        for (int nt = 0; nt < 2; ++nt)
            #pragma unroll
            for (int p = 0; p < 2; ++p) {
                int col = wn + nt * 8 + 2 * tg + p;
                float a = hv[0][nt][p], b = hv[0][nt][p + 2];
                float c2 = hv[1][nt][p], d = hv[1][nt][p + 2];
                atomicAdd(&csum[col], a + b + c2 + d);
                atomicAdd(&csq[col], a * a + b * b + c2 * c2 + d * d);
            }
        __syncthreads();
        if (tid < 64) {
            atomicAdd(&gsum[bn + tid], csum[tid]);
            atomicAdd(&gsq[bn + tid], csq[tid]);
        }
    }
}

__global__ __launch_bounds__(256, 4) void gemm_l1(const float* __restrict__ b1q,
                                                  const float* __restrict__ b1k,
                                                  const float* __restrict__ b1v)
{
    const int p = blockIdx.z;
    const int xi = (p == 0) ? 0 : 1;
    const float* bias = (p == 0) ? b1q : ((p == 1) ? b1k : b1v);
    gemm_core<0, 128>(g_x_hi[xi], g_x_lo[xi], g_w1t[p], bias,
                      g_h1_hi[p], g_h1_lo[p], nullptr, nullptr, nullptr);
}

__global__ __launch_bounds__(256, 4) void gemm_l2(const float* __restrict__ b2q,
                                                  const float* __restrict__ b2k,
                                                  const float* __restrict__ b2v)
{
    const int p = blockIdx.z;
    const float* bias = (p == 0) ? b2q : ((p == 1) ? b2k : b2v);
    gemm_core<1, 256>(g_h1_hi[p], g_h1_lo[p], g_w2t[p], bias,
                      nullptr, nullptr, g_h2[p], g_sum[p], g_sumsq[p]);
}

// -------- attention compute on CSR (vectorized gather) --------
__global__ __launch_bounds__(256) void attn2_kernel(
    const float* __restrict__ gq, const float* __restrict__ bq,
    const float* __restrict__ gk, const float* __restrict__ bk,
    const float* __restrict__ gv, const float* __restrict__ bv,
    float* __restrict__ out)
{
    const int i = blockIdx.x;
    const int tid = threadIdx.x;
    const int lane = tid & 31, wid = tid >> 5;

    __shared__ __align__(16) float qs[FDIM];
    __shared__ __align__(16) float pnum[4][FDIM];
    __shared__ __align__(16) float psub[4][FDIM];
    __shared__ int   snbr[MAXD];
    __shared__ float ez[MAXD];
    __shared__ float red[8];
    __shared__ float s_se, s_cst;

    const int total = g_deg[i];
    if (tid < total) snbr[tid] = g_nbr[(size_t)i * MAXD + tid];

    const float inv = 1.0f / NROWS;
    float m0 = g_sum[0][tid] * inv, v0 = g_sumsq[0][tid] * inv - m0 * m0;
    float sq_ = gq[tid] * rsqrtf(v0 + EPS), shq_ = bq[tid] - m0 * sq_;
    float m1 = g_sum[1][tid] * inv, v1 = g_sumsq[1][tid] * inv - m1 * m1;
    float sk_ = gk[tid] * rsqrtf(v1 + EPS), shk_ = bk[tid] - m1 * sk_;
    float m2 = g_sum[2][tid] * inv, v2 = g_sumsq[2][tid] * inv - m2 * m2;
    float sv_ = gv[tid] * rsqrtf(v2 + EPS), shv_ = bv[tid] - m2 * sv_;

    float qn = fmaf(sq_, g_h2[0][(size_t)i * FDIM + tid], shq_);
    qs[tid] = qn * sk_;
    float cpart = qn * shk_;
    #pragma unroll
    for (int o = 16; o; o >>= 1) cpart += __shfl_xor_sync(0xffffffffu, cpart, o);
    if (lane == 0) red[wid] = cpart;
    __syncthreads();
    if (tid == 0) {
        float r = 0.f;
        #pragma unroll
        for (int w = 0; w < 8; ++w) r += red[w];
        s_cst = r;
    }
    __syncthreads();

    // K-dot products: warps partition neighbors
    const float cst = s_cst;
    const float4* q4 = (const float4*)qs;
    float4 a0 = q4[lane * 2], a1 = q4[lane * 2 + 1];
    const float* Kr = g_h2[1];
    for (int n = wid; n < total; n += 8) {
        const float4* kr = (const float4*)(Kr + (size_t)snbr[n] * FDIM);
        float4 b0 = kr[lane * 2], b1 = kr[lane * 2 + 1];
        float s = a0.x * b0.x + a0.y * b0.y + a0.z * b0.z + a0.w * b0.w
                + a1.x * b1.x + a1.y * b1.y + a1.z * b1.z + a1.w * b1.w;
        #pragma unroll
        for (int o = 16; o; o >>= 1) s += __shfl_xor_sync(0xffffffffu, s, o);
        if (lane == 0) ez[n] = expf((s + cst) * 0.0625f);
    }
    __syncthreads();

    // V accumulation: 4 groups of 64 threads; group grp handles rows n % 4 == grp.
    const int grp = wid >> 1;
    const int t64 = tid & 63;
    const float* Vr = g_h2[2];
    float4 num4 = {0.f, 0.f, 0.f, 0.f};
    float4 sub4 = {0.f, 0.f, 0.f, 0.f};
    for (int n = grp; n < total; n += 4) {
        const float4 v = *(const float4*)(Vr + (size_t)snbr[n] * FDIM + t64 * 4);
        const float e = ez[n];
        num4.x = fmaf(e, v.x, num4.x); num4.y = fmaf(e, v.y, num4.y);
        num4.z = fmaf(e, v.z, num4.z); num4.w = fmaf(e, v.w, num4.w);
        sub4.x += v.x; sub4.y += v.y; sub4.z += v.z; sub4.w += v.w;
    }
    *(float4*)&pnum[grp][t64 * 4] = num4;
    *(float4*)&psub[grp][t64 * 4] = sub4;

    // sum of exp (block reduce)
    float se = 0.f;
    for (int n = tid; n < total; n += 256) se += ez[n];
    #pragma unroll
    for (int o = 16; o; o >>= 1) se += __shfl_xor_sync(0xffffffffu, se, o);
    if (lane == 0) red[wid] = se;
    __syncthreads();
    if (wid == 0) {
        float r = (lane < 8) ? red[lane] : 0.f;
        #pragma unroll
        for (int o = 4; o; o >>= 1) r += __shfl_xor_sync(0xffffffffu, r, o);
        if (lane == 0) s_se = r;
    }
    __syncthreads();
    se = s_se;

    float num = pnum[0][tid] + pnum[1][tid] + pnum[2][tid] + pnum[3][tid];
    float sub = psub[0][tid] + psub[1][tid] + psub[2][tid] + psub[3][tid];

    float totalf = (float)total;
    float denom = ((float)NROWS - totalf) + se;
    float o = (NROWS * bv[tid] + sv_ * (num - sub) + shv_ * (se - totalf)) / denom;
    out[(size_t)i * FDIM + tid] = o;
}

// -------- host --------
extern "C" void kernel_launch(void* const* d_in, const int* in_sizes, int n_in,
                              void* d_out, int out_size)
{
    const float* A = (const float*)d_in[0];
    const float* q = (const float*)d_in[1];
    const float* k = (const float*)d_in[2];
    const float* W1[3] = { (const float*)d_in[3],  (const float*)d_in[9],  (const float*)d_in[15] };
    const float* B1[3] = { (const float*)d_in[4],  (const float*)d_in[10], (const float*)d_in[16] };
    const float* W2[3] = { (const float*)d_in[5],  (const float*)d_in[11], (const float*)d_in[17] };
    const float* B2[3] = { (const float*)d_in[6],  (const float*)d_in[12], (const float*)d_in[18] };
    const float* GM[3] = { (const float*)d_in[7],  (const float*)d_in[13], (const float*)d_in[19] };
    const float* BT[3] = { (const float*)d_in[8],  (const float*)d_in[14], (const float*)d_in[20] };

    static int smem_set = 0;
    const int SMEM_GEMM = 2 * ST_ELEMS * (int)sizeof(f16);   // 30720
    if (!smem_set) {
        cudaFuncSetAttribute(gemm_l1, cudaFuncAttributeMaxDynamicSharedMemorySize, SMEM_GEMM);
        cudaFuncSetAttribute(gemm_l2, cudaFuncAttributeMaxDynamicSharedMemorySize, SMEM_GEMM);
        smem_set = 1;
    }

    scan_prep_kernel<<<NROWS, 256>>>(A, q, k, W1[0], W1[1], W1[2],
                                     W2[0], W2[1], W2[2]);

    dim3 gg(FDIM / 64, NROWS / 64, 3);   // (4, 128, 3) = 1536 blocks
    gemm_l1<<<gg, 256, SMEM_GEMM>>>(B1[0], B1[1], B1[2]);
    gemm_l2<<<gg, 256, SMEM_GEMM>>>(B2[0], B2[1], B2[2]);

    attn2_kernel<<<NROWS, 256>>>(GM[0], BT[0], GM[1], BT[1], GM[2], BT[2],
                                 (float*)d_out);
}

// round 16
// speedup vs baseline: 1.1740x; 1.0159x over previous
#include <cuda_runtime.h>
#include <cuda_fp16.h>
#include <cstdint>
#include <math.h>

#define NROWS 8192
#define FDIM  256
#define EPS   1e-5f
#define SLOPE 0.01f
#define MAXD  128

typedef __half f16;

// -------- scratch (device globals) --------
__device__ f16   g_x_hi[2][NROWS * 128];
__device__ f16   g_x_lo[2][NROWS * 128];
__device__ f16   g_w1t_hi[3][FDIM * 128];
__device__ f16   g_w1t_lo[3][FDIM * 128];
__device__ f16   g_w2t_hi[3][FDIM * FDIM];
__device__ f16   g_w2t_lo[3][FDIM * FDIM];
__device__ f16   g_h1_hi[3][NROWS * FDIM];
__device__ f16   g_h1_lo[3][NROWS * FDIM];
__device__ __align__(16) float g_h2q[NROWS * FDIM];
__device__ __align__(16) f16   g_kv16[2][NROWS * FDIM];
__device__ float g_sum[3][FDIM];
__device__ float g_sumsq[3][FDIM];
__device__ int   g_deg[NROWS];
__device__ int   g_nbr[NROWS * MAXD];

#define MMA_F16(d, a, b) \
    asm volatile("mma.sync.aligned.m16n8k16.row.col.f32.f16.f16.f32 " \
                 "{%0,%1,%2,%3}, {%4,%5,%6,%7}, {%8,%9}, {%0,%1,%2,%3};" \
                 : "+f"(d[0]), "+f"(d[1]), "+f"(d[2]), "+f"(d[3]) \
                 : "r"(a[0]), "r"(a[1]), "r"(a[2]), "r"(a[3]), "r"(b[0]), "r"(b[1]))

#define LDSM4(r, a) \
    asm volatile("ldmatrix.sync.aligned.m8n8.x4.shared.b16 {%0,%1,%2,%3}, [%4];" \
                 : "=r"((r)[0]), "=r"((r)[1]), "=r"((r)[2]), "=r"((r)[3]) : "r"(a))

__device__ __forceinline__ unsigned smem_u32(const void* p) {
    return (unsigned)__cvta_generic_to_shared(p);
}
#define CP16(dst, src) \
    asm volatile("cp.async.cg.shared.global [%0], [%1], 16;" :: "r"(dst), "l"(src))

// stage: A hi/lo 64x40, B hi/lo 64x40 (f16) = 10240 elems = 20KB
#define ST_ELEMS 10240
#define OFF_AH 0
#define OFF_AL 2560
#define OFF_BH 5120
#define OFF_BL 7680

extern __shared__ f16 dsm[];

// -------- fused scan + prep: CSR build + input/weight hi/lo split --------
__global__ __launch_bounds__(256) void scan_prep_kernel(
    const float* __restrict__ A,
    const float* __restrict__ q, const float* __restrict__ k,
    const float* __restrict__ w1q, const float* __restrict__ w1k,
    const float* __restrict__ w1v,
    const float* __restrict__ w2q, const float* __restrict__ w2k,
    const float* __restrict__ w2v)
{
    const int tid = threadIdx.x;
    const int lane = tid & 31, wid = tid >> 5;

    {
        const int idx = blockIdx.x * 256 + tid;
        const int stride = gridDim.x * 256;
        const int NX = NROWS * 128;

        for (int i = idx; i < 3 * FDIM; i += stride) {
            ((float*)g_sum)[i] = 0.f;
            ((float*)g_sumsq)[i] = 0.f;
        }
        for (int i = idx; i < NX; i += stride) {
            float v = q[i];
            f16 h = __float2half_rn(v);
            g_x_hi[0][i] = h;
            g_x_lo[0][i] = __float2half_rn(v - __half2float(h));
            float v2 = k[i];
            f16 h2 = __float2half_rn(v2);
            g_x_hi[1][i] = h2;
            g_x_lo[1][i] = __float2half_rn(v2 - __half2float(h2));
        }
        const float* W1[3] = { w1q, w1k, w1v };
        for (int p = 0; p < 3; ++p) {
            const float* w = W1[p];
            for (int i = idx; i < 128 * FDIM; i += stride) {
                int kk = i / FDIM, n = i % FDIM;
                float v = w[i];
                f16 h = __float2half_rn(v);
                g_w1t_hi[p][n * 128 + kk] = h;
                g_w1t_lo[p][n * 128 + kk] = __float2half_rn(v - __half2float(h));
            }
        }
        const float* W2[3] = { w2q, w2k, w2v };
        for (int p = 0; p < 3; ++p) {
            const float* w = W2[p];
            for (int i = idx; i < FDIM * FDIM; i += stride) {
                int kk = i / FDIM, n = i % FDIM;
                float v = w[i];
                f16 h = __float2half_rn(v);
                g_w2t_hi[p][n * FDIM + kk] = h;
                g_w2t_lo[p][n * FDIM + kk] = __float2half_rn(v - __half2float(h));
            }
        }
    }

    // ---- scan part: one A row per block ----
    __shared__ int wtot[8];
    const int i = blockIdx.x;
    const float4* arow = (const float4*)(A + (size_t)i * NROWS);
    float4 vals[8];
    int cnt = 0;
    #pragma unroll
    for (int it = 0; it < 8; ++it) {
        vals[it] = __ldcs(arow + tid + it * 256);
        cnt += (vals[it].x != 0.f) + (vals[it].y != 0.f) +
               (vals[it].z != 0.f) + (vals[it].w != 0.f);
    }

    int incl = cnt;
    #pragma unroll
    for (int o = 1; o < 32; o <<= 1) {
        int v = __shfl_up_sync(0xffffffffu, incl, o);
        if (lane >= o) incl += v;
    }
    if (lane == 31) wtot[wid] = incl;
    __syncthreads();
    int base = 0, total = 0;
    #pragma unroll
    for (int w = 0; w < 8; ++w) {
        int t = wtot[w];
        if (w < wid) base += t;
        total += t;
    }
    int pos = base + incl - cnt;
    int* nb = g_nbr + (size_t)i * MAXD;
    #pragma unroll
    for (int it = 0; it < 8; ++it) {
        int b4 = (tid + it * 256) * 4;
        if (vals[it].x != 0.f) { if (pos < MAXD) nb[pos] = b4 + 0; pos++; }
        if (vals[it].y != 0.f) { if (pos < MAXD) nb[pos] = b4 + 1; pos++; }
        if (vals[it].z != 0.f) { if (pos < MAXD) nb[pos] = b4 + 2; pos++; }
        if (vals[it].w != 0.f) { if (pos < MAXD) nb[pos] = b4 + 3; pos++; }
    }
    if (tid == 0) g_deg[i] = (total > MAXD) ? MAXD : total;
}

// -------- GEMM core: fp16 3-product (hi*wh + lo*wh + hi*wl) ~ fp32 exact --------
template<int STATS, int K>
__device__ __forceinline__ void gemm_core(
    const f16* __restrict__ Ahi, const f16* __restrict__ Alo,
    const f16* __restrict__ Bhi, const f16* __restrict__ Blo,
    const float* __restrict__ bias,
    f16* __restrict__ OutHi, f16* __restrict__ OutLo,
    float* __restrict__ OutF, f16* __restrict__ Out16,
    float* __restrict__ gsum, float* __restrict__ gsq)
{
    const int tid  = threadIdx.x;
    const int lane = tid & 31, wid = tid >> 5;
    const int g = lane >> 2, tg = lane & 3;
    const int wm = (wid >> 2) * 32;
    const int wn = (wid & 3) * 16;
    const int bm = blockIdx.y * 64, bn = blockIdx.x * 64;

    const int r_ld  = tid >> 2;
    const int cg_ld = (tid & 3) * 8;

    const unsigned offA = (unsigned)(((lane & 7) + ((lane >> 3) & 1) * 8) * 40 + (lane >> 4) * 8);
    const unsigned offB = (unsigned)(((lane & 7) + (lane >> 4) * 8) * 40 + ((lane >> 3) & 1) * 8);

    float acc[2][2][4];
    #pragma unroll
    for (int mt = 0; mt < 2; ++mt)
        #pragma unroll
        for (int nt = 0; nt < 2; ++nt)
            #pragma unroll
            for (int c = 0; c < 4; ++c) acc[mt][nt][c] = 0.f;

    constexpr int nchunks = K >> 5;

    auto load_stage = [&](int st, int k0) {
        f16* base = dsm + st * ST_ELEMS;
        CP16(smem_u32(base + OFF_AH + r_ld * 40 + cg_ld),
             Ahi + (size_t)(bm + r_ld) * K + k0 + cg_ld);
        CP16(smem_u32(base + OFF_AL + r_ld * 40 + cg_ld),
             Alo + (size_t)(bm + r_ld) * K + k0 + cg_ld);
        CP16(smem_u32(base + OFF_BH + r_ld * 40 + cg_ld),
             Bhi + (size_t)(bn + r_ld) * K + k0 + cg_ld);
        CP16(smem_u32(base + OFF_BL + r_ld * 40 + cg_ld),
             Blo + (size_t)(bn + r_ld) * K + k0 + cg_ld);
        asm volatile("cp.async.commit_group;");
    };

    load_stage(0, 0);

    #pragma unroll
    for (int c = 0; c < nchunks; ++c) {
        const int cur = c & 1;
        if (c + 1 < nchunks) {
            load_stage(cur ^ 1, (c + 1) * 32);
            asm volatile("cp.async.wait_group 1;");
        } else {
            asm volatile("cp.async.wait_group 0;");
        }
        __syncthreads();

        const unsigned sb = smem_u32(dsm + cur * ST_ELEMS);
        const unsigned aAh = sb + (OFF_AH + offA) * 2;
        const unsigned aAl = sb + (OFF_AL + offA) * 2;
        const unsigned aBh = sb + (OFF_BH + offB) * 2;
        const unsigned aBl = sb + (OFF_BL + offB) * 2;

        #pragma unroll
        for (int ks = 0; ks < 2; ++ks) {
            const unsigned kb2 = (unsigned)(ks * 16) * 2;
            unsigned int ah[2][4], al[2][4], bf[4];
            const unsigned tom0 = (unsigned)(wm * 40) * 2 + kb2;
            const unsigned tom1 = (unsigned)((wm + 16) * 40) * 2 + kb2;
            const unsigned ton  = (unsigned)(wn * 40) * 2 + kb2;
            LDSM4(ah[0], aAh + tom0);
            LDSM4(ah[1], aAh + tom1);
            LDSM4(al[0], aAl + tom0);
            LDSM4(al[1], aAl + tom1);
            LDSM4(bf, aBh + ton);
            #pragma unroll
            for (int mt = 0; mt < 2; ++mt) {
                MMA_F16(acc[mt][0], ah[mt], (&bf[0]));
                MMA_F16(acc[mt][1], ah[mt], (&bf[2]));
            }
            #pragma unroll
            for (int mt = 0; mt < 2; ++mt) {
                MMA_F16(acc[mt][0], al[mt], (&bf[0]));
                MMA_F16(acc[mt][1], al[mt], (&bf[2]));
            }
            LDSM4(bf, aBl + ton);
            #pragma unroll
            for (int mt = 0; mt < 2; ++mt) {
                MMA_F16(acc[mt][0], ah[mt], (&bf[0]));
                MMA_F16(acc[mt][1], ah[mt], (&bf[2]));
            }
        }
        __syncthreads();
    }

    float hv[2][2][4];
    #pragma unroll
    for (int mt = 0; mt < 2; ++mt)
        #pragma unroll
        for (int nt = 0; nt < 2; ++nt)
            #pragma unroll
            for (int c = 0; c < 4; ++c) {
                int col = wn + nt * 8 + 2 * tg + (c & 1);
                float v = acc[mt][nt][c] + bias[bn + col];
                hv[mt][nt][c] = (v >= 0.f) ? v : SLOPE * v;
            }

    if (STATS == 0) {
        #pragma unroll
        for (int mt = 0; mt < 2; ++mt)
            #pragma unroll
            for (int nt = 0; nt < 2; ++nt)
                #pragma unroll
                for (int c = 0; c < 4; ++c) {
                    int row = bm + wm + mt * 16 + g + ((c >> 1) ? 8 : 0);
                    int col = bn + wn + nt * 8 + 2 * tg + (c & 1);
                    float v = hv[mt][nt][c];
                    f16 h = __float2half_rn(v);
                    size_t idx = (size_t)row * FDIM + col;
                    OutHi[idx] = h;
                    OutLo[idx] = __float2half_rn(v - __half2float(h));
                }
    } else {
        #pragma unroll
        for (int mt = 0; mt < 2; ++mt)
            #pragma unroll
            for (int nt = 0; nt < 2; ++nt)
                #pragma unroll
                for (int c = 0; c < 4; ++c) {
                    int row = bm + wm + mt * 16 + g + ((c >> 1) ? 8 : 0);
                    int col = bn + wn + nt * 8 + 2 * tg + (c & 1);
                    size_t idx = (size_t)row * FDIM + col;
                    if (OutF) OutF[idx] = hv[mt][nt][c];
                    else      Out16[idx] = __float2half_rn(hv[mt][nt][c]);
                }
        float* csum = (float*)dsm;
        float* csq  = csum + 64;
        if (tid < 128) ((float*)dsm)[tid] = 0.f;
        __syncthreads();
        #pragma unroll
        for (int nt = 0; nt < 2; ++nt)
            #pragma unroll
            for (int p = 0; p < 2; ++p) {
                int col = wn + nt * 8 + 2 * tg + p;
                float a = hv[0][nt][p], b = hv[0][nt][p + 2];
                float c2 = hv[1][nt][p], d = hv[1][nt][p + 2];
                atomicAdd(&csum[col], a + b + c2 + d);
                atomicAdd(&csq[col], a * a + b * b + c2 * c2 + d * d);
            }
        __syncthreads();
        if (tid < 64) {
            atomicAdd(&gsum[bn + tid], csum[tid]);
            atomicAdd(&gsq[bn + tid], csq[tid]);
        }
    }
}

__global__ __launch_bounds__(256, 4) void gemm_l1(const float* __restrict__ b1q,
                                                  const float* __restrict__ b1k,
                                                  const float* __restrict__ b1v)
{
    const int p = blockIdx.z;
    const int xi = (p == 0) ? 0 : 1;
    const float* bias = (p == 0) ? b1q : ((p == 1) ? b1k : b1v);
    gemm_core<0, 128>(g_x_hi[xi], g_x_lo[xi], g_w1t_hi[p], g_w1t_lo[p], bias,
                      g_h1_hi[p], g_h1_lo[p], nullptr, nullptr, nullptr, nullptr);
}

__global__ __launch_bounds__(256, 4) void gemm_l2(const float* __restrict__ b2q,
                                                  const float* __restrict__ b2k,
                                                  const float* __restrict__ b2v)
{
    const int p = blockIdx.z;
    const float* bias = (p == 0) ? b2q : ((p == 1) ? b2k : b2v);
    float* outF = (p == 0) ? g_h2q : nullptr;
    f16* out16 = (p == 0) ? nullptr : g_kv16[p - 1];
    gemm_core<1, 256>(g_h1_hi[p], g_h1_lo[p], g_w2t_hi[p], g_w2t_lo[p], bias,
                      nullptr, nullptr, outF, out16, g_sum[p], g_sumsq[p]);
}

// -------- attention compute on CSR; K/V gathered as fp16 --------
__global__ __launch_bounds__(256) void attn2_kernel(
    const float* __restrict__ gq, const float* __restrict__ bq,
    const float* __restrict__ gk, const float* __restrict__ bk,
    const float* __restrict__ gv, const float* __restrict__ bv,
    float* __restrict__ out)
{
    const int i = blockIdx.x;
    const int tid = threadIdx.x;
    const int lane = tid & 31, wid = tid >> 5;

    __shared__ __align__(16) float qs[FDIM];
    __shared__ __align__(16) float pnum[4][FDIM];
    __shared__ __align__(16) float psub[4][FDIM];
    __shared__ int   snbr[MAXD];
    __shared__ float ez[MAXD];
    __shared__ float red[8];
    __shared__ float s_se, s_cst;

    const int total = g_deg[i];
    if (tid < total) snbr[tid] = g_nbr[(size_t)i * MAXD + tid];

    const float inv = 1.0f / NROWS;
    float m0 = g_sum[0][tid] * inv, v0 = g_sumsq[0][tid] * inv - m0 * m0;
    float sq_ = gq[tid] * rsqrtf(v0 + EPS), shq_ = bq[tid] - m0 * sq_;
    float m1 = g_sum[1][tid] * inv, v1 = g_sumsq[1][tid] * inv - m1 * m1;
    float sk_ = gk[tid] * rsqrtf(v1 + EPS), shk_ = bk[tid] - m1 * sk_;
    float m2 = g_sum[2][tid] * inv, v2 = g_sumsq[2][tid] * inv - m2 * m2;
    float sv_ = gv[tid] * rsqrtf(v2 + EPS), shv_ = bv[tid] - m2 * sv_;

    float qn = fmaf(sq_, g_h2q[(size_t)i * FDIM + tid], shq_);
    qs[tid] = qn * sk_;
    float cpart = qn * shk_;
    #pragma unroll
    for (int o = 16; o; o >>= 1) cpart += __shfl_xor_sync(0xffffffffu, cpart, o);
    if (lane == 0) red[wid] = cpart;
    __syncthreads();
    if (tid == 0) {
        float r = 0.f;
        #pragma unroll
        for (int w = 0; w < 8; ++w) r += red[w];
        s_cst = r;
    }
    __syncthreads();

    // K-dot products vs fp16 raw K rows; lane covers 8 features (one uint4)
    const float cst = s_cst;
    const float4* q4 = (const float4*)qs;
    float4 a0 = q4[lane * 2], a1 = q4[lane * 2 + 1];
    const f16* Kr = g_kv16[0];
    for (int n = wid; n < total; n += 8) {
        uint4 kv = *(const uint4*)(Kr + (size_t)snbr[n] * FDIM + lane * 8);
        const __half2* hp = (const __half2*)&kv;
        float2 k0 = __half22float2(hp[0]);
        float2 k1 = __half22float2(hp[1]);
        float2 k2 = __half22float2(hp[2]);
        float2 k3 = __half22float2(hp[3]);
        float s = a0.x * k0.x + a0.y * k0.y + a0.z * k1.x + a0.w * k1.y
                + a1.x * k2.x + a1.y * k2.y + a1.z * k3.x + a1.w * k3.y;
        #pragma unroll
        for (int o = 16; o; o >>= 1) s += __shfl_xor_sync(0xffffffffu, s, o);
        if (lane == 0) ez[n] = expf((s + cst) * 0.0625f);
    }
    __syncthreads();

    // V accumulation: 4 groups of 64 threads; rows n % 4 == grp; fp16 loads (8B)
    const int grp = wid >> 1;
    const int t64 = tid & 63;
    const f16* Vr = g_kv16[1];
    float4 num4 = {0.f, 0.f, 0.f, 0.f};
    float4 sub4 = {0.f, 0.f, 0.f, 0.f};
    for (int n = grp; n < total; n += 4) {
        uint2 vv = *(const uint2*)(Vr + (size_t)snbr[n] * FDIM + t64 * 4);
        const __half2* vp = (const __half2*)&vv;
        float2 v0 = __half22float2(vp[0]);
        float2 v1 = __half22float2(vp[1]);
        const float e = ez[n];
        num4.x = fmaf(e, v0.x, num4.x); num4.y = fmaf(e, v0.y, num4.y);
        num4.z = fmaf(e, v1.x, num4.z); num4.w = fmaf(e, v1.y, num4.w);
        sub4.x += v0.x; sub4.y += v0.y; sub4.z += v1.x; sub4.w += v1.y;
    }
    *(float4*)&pnum[grp][t64 * 4] = num4;
    *(float4*)&psub[grp][t64 * 4] = sub4;

    // sum of exp (block reduce)
    float se = 0.f;
    for (int n = tid; n < total; n += 256) se += ez[n];
    #pragma unroll
    for (int o = 16; o; o >>= 1) se += __shfl_xor_sync(0xffffffffu, se, o);
    if (lane == 0) red[wid] = se;
    __syncthreads();
    if (wid == 0) {
        float r = (lane < 8) ? red[lane] : 0.f;
        #pragma unroll
        for (int o = 4; o; o >>= 1) r += __shfl_xor_sync(0xffffffffu, r, o);
        if (lane == 0) s_se = r;
    }
    __syncthreads();
    se = s_se;

    float num = pnum[0][tid] + pnum[1][tid] + pnum[2][tid] + pnum[3][tid];
    float sub = psub[0][tid] + psub[1][tid] + psub[2][tid] + psub[3][tid];

    float totalf = (float)total;
    float denom = ((float)NROWS - totalf) + se;
    float o = (NROWS * bv[tid] + sv_ * (num - sub) + shv_ * (se - totalf)) / denom;
    out[(size_t)i * FDIM + tid] = o;
}

// -------- host --------
extern "C" void kernel_launch(void* const* d_in, const int* in_sizes, int n_in,
                              void* d_out, int out_size)
{
    const float* A = (const float*)d_in[0];
    const float* q = (const float*)d_in[1];
    const float* k = (const float*)d_in[2];
    const float* W1[3] = { (const float*)d_in[3],  (const float*)d_in[9],  (const float*)d_in[15] };
    const float* B1[3] = { (const float*)d_in[4],  (const float*)d_in[10], (const float*)d_in[16] };
    const float* W2[3] = { (const float*)d_in[5],  (const float*)d_in[11], (const float*)d_in[17] };
    const float* B2[3] = { (const float*)d_in[6],  (const float*)d_in[12], (const float*)d_in[18] };
    const float* GM[3] = { (const float*)d_in[7],  (const float*)d_in[13], (const float*)d_in[19] };
    const float* BT[3] = { (const float*)d_in[8],  (const float*)d_in[14], (const float*)d_in[20] };

    static int smem_set = 0;
    const int SMEM_GEMM = 2 * ST_ELEMS * (int)sizeof(f16);   // 40960
    if (!smem_set) {
        cudaFuncSetAttribute(gemm_l1, cudaFuncAttributeMaxDynamicSharedMemorySize, SMEM_GEMM);
        cudaFuncSetAttribute(gemm_l2, cudaFuncAttributeMaxDynamicSharedMemorySize, SMEM_GEMM);
        smem_set = 1;
    }

    scan_prep_kernel<<<NROWS, 256>>>(A, q, k, W1[0], W1[1], W1[2],
                                     W2[0], W2[1], W2[2]);

    dim3 gg(FDIM / 64, NROWS / 64, 3);   // (4, 128, 3) = 1536 blocks
    gemm_l1<<<gg, 256, SMEM_GEMM>>>(B1[0], B1[1], B1[2]);
    gemm_l2<<<gg, 256, SMEM_GEMM>>>(B2[0], B2[1], B2[2]);

    attn2_kernel<<<NROWS, 256>>>(GM[0], BT[0], GM[1], BT[1], GM[2], BT[2],
                                 (float*)d_out);
}